// round 12
// baseline (speedup 1.0000x reference)
#include <cuda_runtime.h>
#include <cstdint>

// ---------------- scratch (static device globals; no allocations) ----------
__device__ float g_h1p[32u*64*66*66];    // conv1 out, padded NCHW [32][64][66][66]
__device__ float g_w1f[4608];            // (unused by scalar conv1; prep still fills)
__device__ float g_w2f[9*8192];          // conv2 weights, mma-fragment order (tf32)
__device__ float g_wqkv[24576];          // qkv weights [192 x 128], fragment order
__device__ float g_f [32u*32*32*128];    // conv2 out, NHWC, tf32-rounded values
__device__ float g_fpart[1024*128];      // per-conv2-CTA column sums of f (exact)
__device__ float g_q [32u*4*1024*16];    // [b,head,y,x,d]
__device__ float g_k [32u*4*1024*16];
__device__ float g_v [32u*4*1024*16];
__device__ float g_osum[128*16];         // per-(b,head) sum over tokens of (o_row+o_col)

// ---------------- helpers ----------------------------------------------------
__device__ __forceinline__ uint32_t smem_u32(const void* p) {
    uint32_t a;
    asm("{ .reg .u64 t; cvta.to.shared.u64 t, %1; cvt.u32.u64 %0, t; }"
        : "=r"(a) : "l"(p));
    return a;
}
__device__ __forceinline__ float tf32r(float x) {
    uint32_t u;
    asm("cvt.rna.tf32.f32 %0, %1;" : "=r"(u) : "f"(x));
    return __uint_as_float(u);
}
__device__ __forceinline__ void cpa16(uint32_t d, const void* s) {
    asm volatile("cp.async.cg.shared.global [%0], [%1], 16;" :: "r"(d), "l"(s));
}
__device__ __forceinline__ void cpa8(uint32_t d, const void* s) {
    asm volatile("cp.async.ca.shared.global [%0], [%1], 8;" :: "r"(d), "l"(s));
}
__device__ __forceinline__ void mma16n8k8(float* c, const uint32_t* a, const uint32_t* b) {
    asm volatile("mma.sync.aligned.m16n8k8.row.col.f32.tf32.tf32.f32 "
        "{%0,%1,%2,%3}, {%4,%5,%6,%7}, {%8,%9}, {%0,%1,%2,%3};"
        : "+f"(c[0]), "+f"(c[1]), "+f"(c[2]), "+f"(c[3])
        : "r"(a[0]), "r"(a[1]), "r"(a[2]), "r"(a[3]), "r"(b[0]), "r"(b[1]));
}
__device__ __forceinline__ float dot16(float4 q0, float4 q1, float4 q2, float4 q3,
                                       const float4* kp) {
    float4 k0 = kp[0], k1 = kp[1], k2 = kp[2], k3 = kp[3];
    float s = q0.x*k0.x;
    s = fmaf(q0.y, k0.y, s); s = fmaf(q0.z, k0.z, s); s = fmaf(q0.w, k0.w, s);
    s = fmaf(q1.x, k1.x, s); s = fmaf(q1.y, k1.y, s); s = fmaf(q1.z, k1.z, s); s = fmaf(q1.w, k1.w, s);
    s = fmaf(q2.x, k2.x, s); s = fmaf(q2.y, k2.y, s); s = fmaf(q2.z, k2.z, s); s = fmaf(q2.w, k2.w, s);
    s = fmaf(q3.x, k3.x, s); s = fmaf(q3.y, k3.y, s); s = fmaf(q3.z, k3.z, s); s = fmaf(q3.w, k3.w, s);
    return s;
}

// ---------------- merged prep: w2f | wqkv | w1f | h1p border zero -----------
__global__ __launch_bounds__(256) void prep_kernel(const float* __restrict__ w2,
                                                   const float* __restrict__ qw,
                                                   const float* __restrict__ kw,
                                                   const float* __restrict__ vw,
                                                   const float* __restrict__ w1) {
    int blk = blockIdx.x, tid = threadIdx.x;
    if (blk < 288) {                       // conv2 weights -> fragment order
        int i = blk * 256 + tid;
        int t = i / 8192;
        int r = i - t * 8192;
        int z = r & 1;
        int lane = (r >> 1) & 31;
        int idx2 = r >> 6;
        int nf = idx2 & 15, ks = idx2 >> 4;
        int co = nf * 8 + (lane >> 2);
        int ci = ks * 8 + (lane & 3) + 4 * z;
        g_w2f[i] = tf32r(w2[(co * 64 + ci) * 9 + t]);
    } else if (blk < 384) {                // qkv weights -> fragment order
        int i = (blk - 288) * 256 + tid;
        int z = i & 1;
        int lane = (i >> 1) & 31;
        int rest = i >> 6;
        int nf = rest % 24, ks = rest / 24;
        int o = nf * 8 + (lane >> 2);
        int k = ks * 8 + (lane & 3) + 4 * z;
        float v;
        if (o < 64)       v = qw[o*128 + k] * 0.25f;
        else if (o < 128) v = kw[(o-64)*128 + k];
        else              v = vw[(o-128)*128 + k];
        g_wqkv[i] = tf32r(v);
    } else if (blk < 402) {                // conv1 weights (kept; harmless)
        int i = (blk - 384) * 256 + tid;
        int t = i >> 9;
        int j = i & 511;
        int nf = j >> 6, jj = j & 63;
        int lane = jj >> 1, z = jj & 1;
        int co = nf * 8 + (lane >> 2);
        int ci = (lane & 3) + 4 * z;
        g_w1f[i] = (ci < 3) ? tf32r(w1[co * 27 + ci * 9 + t]) : 0.f;
    } else {                               // zero h1p borders
        int b = blk - 402;
        float* hb = g_h1p + (size_t)b * 64 * 4356;
        for (int i = tid; i < 16640; i += 256) {
            int co = i / 260, j = i % 260;
            int p, q;
            if (j < 66)       { p = 0;           q = j; }
            else if (j < 132) { p = 65;          q = j - 66; }
            else if (j < 196) { p = j - 132 + 1; q = 0; }
            else              { p = j - 196 + 1; q = 65; }
            hb[(size_t)co * 4356 + p * 66 + q] = 0.f;
        }
    }
}

// ---------------- conv1 scalar (float4 weight loads): conv+relu+maxpool -----
__global__ __launch_bounds__(256) void conv1_kernel(const float* __restrict__ x,
                                                    const float* __restrict__ w,
                                                    const float* __restrict__ bias) {
    __shared__ float s_in[3*34*34];
    __shared__ float s_w[64*28];          // stride 28 (112B, 16B-aligned rows)
    __shared__ float s_b[64];
    int b  = blockIdx.y;
    int tY = blockIdx.x >> 2, tX = blockIdx.x & 3;
    int Py0 = tY*16, Px0 = tX*16;
    int tid = threadIdx.x;

    for (int i = tid; i < 64*27; i += 256) {
        int co = i / 27, k = i - co*27;
        s_w[co*28 + k] = w[i];
    }
    if (tid < 64) { s_b[tid] = bias[tid]; s_w[tid*28 + 27] = 0.f; }

    const float* xb = x + (size_t)b*3*128*128;
    for (int i = tid; i < 3*34*34; i += 256) {
        int ci = i / 1156, rem2 = i % 1156;
        int ly = rem2 / 34, lx = rem2 % 34;
        int gy = 2*Py0 - 1 + ly, gx = 2*Px0 - 1 + lx;
        float v = 0.f;
        if (gy >= 0 && gy < 128 && gx >= 0 && gx < 128)
            v = xb[(size_t)ci*16384 + gy*128 + gx];
        s_in[i] = v;
    }
    __syncthreads();

    int ty = tid >> 4, tx = tid & 15;
    float win[3][16];
    #pragma unroll
    for (int ci = 0; ci < 3; ci++)
        #pragma unroll
        for (int r = 0; r < 4; r++)
            #pragma unroll
            for (int c = 0; c < 4; c++)
                win[ci][r*4+c] = s_in[ci*1156 + (2*ty + r)*34 + (2*tx + c)];

    int Y = Py0 + ty, X = Px0 + tx;
    float* outp = g_h1p + (size_t)b*64*4356 + (size_t)(Y+1)*66 + (X+1);
    #pragma unroll 1
    for (int co = 0; co < 64; co++) {
        float wv[28];
        const float4* wp4 = reinterpret_cast<const float4*>(&s_w[co*28]);
        #pragma unroll
        for (int q4 = 0; q4 < 7; q4++) {
            float4 t4 = wp4[q4];
            wv[q4*4+0] = t4.x; wv[q4*4+1] = t4.y;
            wv[q4*4+2] = t4.z; wv[q4*4+3] = t4.w;
        }
        float a0=0.f, a1=0.f, a2=0.f, a3=0.f;
        #pragma unroll
        for (int ci = 0; ci < 3; ci++)
            #pragma unroll
            for (int k = 0; k < 9; k++) {
                int ky = k/3, kx = k%3;
                float wvv = wv[ci*9+k];
                a0 = fmaf(win[ci][ ky   *4 + kx    ], wvv, a0);
                a1 = fmaf(win[ci][ ky   *4 + kx + 1], wvv, a1);
                a2 = fmaf(win[ci][(ky+1)*4 + kx    ], wvv, a2);
                a3 = fmaf(win[ci][(ky+1)*4 + kx + 1], wvv, a3);
            }
        float m = fmaxf(fmaxf(a0,a1), fmaxf(a2,a3));
        outp[(size_t)co*4356] = tf32r(fmaxf(m + s_b[co], 0.f));
    }
}

// ---------------- conv2 via mma.sync tf32 (9 taps, M=128, half-tap ping-pong)
__global__ __launch_bounds__(256, 2) void conv2_mma_kernel(const float* __restrict__ b2) {
    extern __shared__ float sm[];
    const int tid = threadIdx.x;
    const int lane = tid & 31, wid = tid >> 5;
    const int warp_m = wid >> 1, warp_n = wid & 1;
    const int bY = blockIdx.x;
    const int b = bY >> 5, Y = bY & 31;

    uint32_t slab_b = smem_u32(sm);
    const uint32_t bufB[2] = { slab_b + 16896u*4u, slab_b + 20992u*4u };

    {
        const float* sb0 = g_h1p + (size_t)b*278784 + 132*Y;
        for (int i = tid; i < 8448; i += 256) {
            int ci = i / 132, w2i = i - ci*132;
            cpa8(slab_b + (uint32_t)i*8u, sb0 + (size_t)ci*4356 + w2i*2);
        }
        for (int i = tid; i < 1024; i += 256)
            cpa16(bufB[0] + (uint32_t)i*16u, g_w2f + i*4);
        asm volatile("cp.async.commit_group;" ::: "memory");
        for (int i = tid; i < 1024; i += 256)
            cpa16(bufB[1] + (uint32_t)i*16u, g_w2f + 4096 + i*4);
        asm volatile("cp.async.commit_group;" ::: "memory");
    }

    float c[2][8][4];
    #pragma unroll
    for (int mf = 0; mf < 2; mf++)
        #pragma unroll
        for (int nf = 0; nf < 8; nf++)
            #pragma unroll
            for (int r = 0; r < 4; r++) c[mf][nf][r] = 0.f;

    const int ry  = warp_m >> 1;
    const int xw0 = (warp_m & 1) * 32;

    #pragma unroll 1
    for (int ch = 0; ch < 18; ch++) {
        if (ch < 17) { asm volatile("cp.async.wait_group 1;" ::: "memory"); }
        else         { asm volatile("cp.async.wait_group 0;" ::: "memory"); }
        __syncthreads();

        const int t = ch >> 1, half = ch & 1;
        const int ky = t / 3, kx = t - ky*3;
        const float* Abase = sm + (ry + ky)*66 + kx + xw0 + (lane >> 2) + (lane & 3)*264;
        const float* Bbase = sm + 16896 + half*4096 + warp_n*512 + lane*2;
        #pragma unroll
        for (int ksl = 0; ksl < 4; ksl++) {
            const int ks = half*4 + ksl;
            const float* Ak = Abase + ks*2112;
            uint32_t a[2][4];
            #pragma unroll
            for (int mf = 0; mf < 2; mf++) {
                const float* Am = Ak + mf*16;
                a[mf][0] = __float_as_uint(Am[0]);
                a[mf][1] = __float_as_uint(Am[8]);
                a[mf][2] = __float_as_uint(Am[1056]);
                a[mf][3] = __float_as_uint(Am[1064]);
            }
            const float* Bk = Bbase + ksl*1024;
            uint32_t bb[8][2];
            #pragma unroll
            for (int nf = 0; nf < 8; nf++) {
                float2 v = *reinterpret_cast<const float2*>(Bk + nf*64);
                bb[nf][0] = __float_as_uint(v.x);
                bb[nf][1] = __float_as_uint(v.y);
            }
            #pragma unroll
            for (int mf = 0; mf < 2; mf++)
                #pragma unroll
                for (int nf = 0; nf < 8; nf++)
                    mma16n8k8(c[mf][nf], a[mf], bb[nf]);
        }

        __syncthreads();
        if (ch < 16) {
            const int cn = ch + 2;
            const float* wsrc = g_w2f + (cn >> 1)*8192 + (cn & 1)*4096;
            uint32_t dst = bufB[cn & 1];
            for (int i = tid; i < 1024; i += 256)
                cpa16(dst + (uint32_t)i*16u, wsrc + i*4);
            asm volatile("cp.async.commit_group;" ::: "memory");
        }
    }

    // ---- epilogue: stage C [128][132], pool+bias+relu ----
    #pragma unroll
    for (int mf = 0; mf < 2; mf++)
        #pragma unroll
        for (int nf = 0; nf < 8; nf++) {
            int m0 = warp_m*32 + mf*16 + (lane >> 2);
            int n0 = warp_n*64 + nf*8 + (lane & 3)*2;
            *reinterpret_cast<float2*>(sm + m0*132 + n0)     = make_float2(c[mf][nf][0], c[mf][nf][1]);
            *reinterpret_cast<float2*>(sm + (m0+8)*132 + n0) = make_float2(c[mf][nf][2], c[mf][nf][3]);
        }
    __syncthreads();
    float* gf = g_f + (((size_t)b*32 + Y)*32)*128;
    float fsum = 0.f;
    #pragma unroll
    for (int u = 0; u < 16; u++) {
        int idx = tid + u*256;
        int cch = idx & 127, xo = idx >> 7;
        float v0 = fmaxf(sm[(2*xo)*132 + cch],    sm[(2*xo+1)*132 + cch]);
        float v1 = fmaxf(sm[(64+2*xo)*132 + cch], sm[(64+2*xo+1)*132 + cch]);
        float v = fmaxf(fmaxf(v0, v1) + __ldg(&b2[cch]), 0.f);
        fsum += v;
        gf[(size_t)xo*128 + cch] = tf32r(v);
    }
    float* red = sm + 20480;
    red[tid] = fsum;
    __syncthreads();
    if (tid < 128) g_fpart[(size_t)bY*128 + tid] = red[tid] + red[tid+128];
}

// ---------------- qkv via mma.sync tf32 + smem-staged coalesced stores ------
__global__ __launch_bounds__(256) void qkv_mma_kernel(
    const float* __restrict__ qb, const float* __restrict__ kb,
    const float* __restrict__ vb) {
    extern __shared__ float sm[];
    const int tid = threadIdx.x;
    const int lane = tid & 31, wid = tid >> 5;
    const int warp_m = wid >> 1, warp_n = wid & 1;
    uint32_t smb = smem_u32(sm);

    {
        const float* gf0 = g_f + (size_t)blockIdx.x * 16384;
        for (int i = tid; i < 4096; i += 256) {
            int row = i >> 5, cg = i & 31;
            cpa16(smb + (uint32_t)(row * 132 + cg * 4) * 4u, gf0 + i * 4);
        }
        uint32_t bsb = smb + 16896u * 4u;
        for (int i = tid; i < 6144; i += 256)
            cpa16(bsb + (uint32_t)i * 16u, g_wqkv + i * 4);
        asm volatile("cp.async.commit_group;" ::: "memory");
        asm volatile("cp.async.wait_group 0;" ::: "memory");
    }
    __syncthreads();

    float c[2][12][4];
    #pragma unroll
    for (int mf = 0; mf < 2; mf++)
        #pragma unroll
        for (int nf = 0; nf < 12; nf++)
            #pragma unroll
            for (int r = 0; r < 4; r++) c[mf][nf][r] = 0.f;

    const float* Ab = sm + (warp_m * 32 + (lane >> 2)) * 132 + (lane & 3);
    const float* Bb = sm + 16896 + (warp_n * 12 * 64) + lane * 2;

    #pragma unroll 1
    for (int ks = 0; ks < 16; ks++) {
        uint32_t a[2][4];
        const float* Ak = Ab + ks * 8;
        #pragma unroll
        for (int mf = 0; mf < 2; mf++) {
            const float* Am = Ak + mf * 2112;
            a[mf][0] = __float_as_uint(Am[0]);
            a[mf][1] = __float_as_uint(Am[1056]);
            a[mf][2] = __float_as_uint(Am[4]);
            a[mf][3] = __float_as_uint(Am[1060]);
        }
        const float* Bk = Bb + ks * 1536;
        uint32_t bb[12][2];
        #pragma unroll
        for (int nf = 0; nf < 12; nf++) {
            float2 v = *reinterpret_cast<const float2*>(Bk + nf * 64);
            bb[nf][0] = __float_as_uint(v.x);
            bb[nf][1] = __float_as_uint(v.y);
        }
        #pragma unroll
        for (int mf = 0; mf < 2; mf++)
            #pragma unroll
            for (int nf = 0; nf < 12; nf++)
                mma16n8k8(c[mf][nf], a[mf], bb[nf]);
    }

    // ---- stage 128x192 output tile (stride 196), then coalesced writes ----
    __syncthreads();                       // A/B smem reuse
    #pragma unroll
    for (int mf = 0; mf < 2; mf++)
        #pragma unroll
        for (int nf = 0; nf < 12; nf++) {
            int m0 = warp_m*32 + mf*16 + (lane >> 2);
            int o  = warp_n*96 + nf*8 + (lane & 3)*2;
            *reinterpret_cast<float2*>(sm + m0*196 + o)     = make_float2(c[mf][nf][0], c[mf][nf][1]);
            *reinterpret_cast<float2*>(sm + (m0+8)*196 + o) = make_float2(c[mf][nf][2], c[mf][nf][3]);
        }
    __syncthreads();

    const int bb_  = blockIdx.x >> 3;
    const int t0   = (blockIdx.x & 7) * 128;
    #pragma unroll 1
    for (int it = 0; it < 24; it++) {
        int e = tid + it*256;              // over 6144 float4s
        int seg = e >> 9, j4 = e & 511;    // seg = mat*4 + head
        int token = j4 >> 2, dq = (j4 & 3) * 4;
        int mat = seg >> 2, head = seg & 3;
        int o = seg*16 + dq;
        const float* sp = sm + token*196 + o;
        float4 v = make_float4(sp[0], sp[1], sp[2], sp[3]);
        float* basep; const float* biasp; float bscale;
        if (mat == 0)      { basep = g_q; biasp = qb; bscale = 0.25f; }
        else if (mat == 1) { basep = g_k; biasp = kb; bscale = 1.f; }
        else               { basep = g_v; biasp = vb; bscale = 1.f; }
        int ob = head*16 + dq;             // bias index base within 64
        v.x += __ldg(&biasp[ob+0]) * bscale;
        v.y += __ldg(&biasp[ob+1]) * bscale;
        v.z += __ldg(&biasp[ob+2]) * bscale;
        v.w += __ldg(&biasp[ob+3]) * bscale;
        float* gp = basep + ((size_t)(bb_*4 + head)*1024 + t0 + token)*16 + dq;
        *reinterpret_cast<float4*>(gp) = v;
    }
}

// ---------------- fused axial attention (row + col), one CTA per (b,head) ---
__global__ __launch_bounds__(256) void attn_fused_kernel(const float* __restrict__ rel_w,
                                                         const float* __restrict__ rel_h) {
    extern __shared__ float asmem[];
    float* ks  = asmem;
    float* vs  = asmem + 16384;
    float* srw = asmem + 32768;
    float* srh = asmem + 32832;
    const int bh = blockIdx.x;
    const int head = bh & 3;
    const int tid = threadIdx.x;
    const int l = tid & 31, w = tid >> 5;

    {
        const float4* gk = (const float4*)(g_k + (size_t)bh * 16384);
        const float4* gv = (const float4*)(g_v + (size_t)bh * 16384);
        float4* k4 = (float4*)ks;
        float4* v4 = (float4*)vs;
        for (int i = tid; i < 4096; i += 256) { k4[i] = gk[i]; v4[i] = gv[i]; }
        if (tid < 63) { srw[tid] = rel_w[head*63 + tid]; srh[tid] = rel_h[head*63 + tid]; }
    }
    __syncthreads();

    const float* gq = g_q + (size_t)bh * 16384;
    float4 acc0 = {0,0,0,0}, acc1 = {0,0,0,0}, acc2 = {0,0,0,0}, acc3 = {0,0,0,0};

    #pragma unroll 1
    for (int u = 0; u < 4; u++) {
        const int y = w + 8*u;
        const int t = y*32 + l;
        const float4* qp = (const float4*)(gq + t*16);
        const float4 q0 = qp[0], q1 = qp[1], q2 = qp[2], q3 = qp[3];
        float sc[32];
        float mx = -1e30f;
        #pragma unroll
        for (int j = 0; j < 32; j++) {
            float s = dot16(q0, q1, q2, q3, (const float4*)(ks + (y*32 + j)*16));
            s += srw[l - j + 31];
            sc[j] = s;
            mx = fmaxf(mx, s);
        }
        float ssum = 0.f;
        #pragma unroll
        for (int j = 0; j < 32; j++) { sc[j] = __expf(sc[j] - mx); ssum += sc[j]; }
        const float inv = 1.f / ssum;
        float4 o0 = {0,0,0,0}, o1 = {0,0,0,0}, o2 = {0,0,0,0}, o3 = {0,0,0,0};
        #pragma unroll
        for (int j = 0; j < 32; j++) {
            const float4* vp = (const float4*)(vs + (y*32 + j)*16);
            const float p = sc[j];
            float4 v0 = vp[0], v1 = vp[1], v2 = vp[2], v3 = vp[3];
            o0.x = fmaf(p, v0.x, o0.x); o0.y = fmaf(p, v0.y, o0.y);
            o0.z = fmaf(p, v0.z, o0.z); o0.w = fmaf(p, v0.w, o0.w);
            o1.x = fmaf(p, v1.x, o1.x); o1.y = fmaf(p, v1.y, o1.y);
            o1.z = fmaf(p, v1.z, o1.z); o1.w = fmaf(p, v1.w, o1.w);
            o2.x = fmaf(p, v2.x, o2.x); o2.y = fmaf(p, v2.y, o2.y);
            o2.z = fmaf(p, v2.z, o2.z); o2.w = fmaf(p, v2.w, o2.w);
            o3.x = fmaf(p, v3.x, o3.x); o3.y = fmaf(p, v3.y, o3.y);
            o3.z = fmaf(p, v3.z, o3.z); o3.w = fmaf(p, v3.w, o3.w);
        }
        acc0.x = fmaf(o0.x, inv, acc0.x); acc0.y = fmaf(o0.y, inv, acc0.y);
        acc0.z = fmaf(o0.z, inv, acc0.z); acc0.w = fmaf(o0.w, inv, acc0.w);
        acc1.x = fmaf(o1.x, inv, acc1.x); acc1.y = fmaf(o1.y, inv, acc1.y);
        acc1.z = fmaf(o1.z, inv, acc1.z); acc1.w = fmaf(o1.w, inv, acc1.w);
        acc2.x = fmaf(o2.x, inv, acc2.x); acc2.y = fmaf(o2.y, inv, acc2.y);
        acc2.z = fmaf(o2.z, inv, acc2.z); acc2.w = fmaf(o2.w, inv, acc2.w);
        acc3.x = fmaf(o3.x, inv, acc3.x); acc3.y = fmaf(o3.y, inv, acc3.y);
        acc3.z = fmaf(o3.z, inv, acc3.z); acc3.w = fmaf(o3.w, inv, acc3.w);
    }

    #pragma unroll 1
    for (int u = 0; u < 4; u++) {
        const int x = w + 8*u;
        const int t = l*32 + x;
        const float4* qp = (const float4*)(gq + t*16);
        const float4 q0 = qp[0], q1 = qp[1], q2 = qp[2], q3 = qp[3];
        float sc[32];
        float mx = -1e30f;
        #pragma unroll
        for (int i = 0; i < 32; i++) {
            float s = dot16(q0, q1, q2, q3, (const float4*)(ks + (i*32 + x)*16));
            s += srh[l - i + 31];
            sc[i] = s;
            mx = fmaxf(mx, s);
        }
        float ssum = 0.f;
        #pragma unroll
        for (int i = 0; i < 32; i++) { sc[i] = __expf(sc[i] - mx); ssum += sc[i]; }
        const float inv = 1.f / ssum;
        float4 o0 = {0,0,0,0}, o1 = {0,0,0,0}, o2 = {0,0,0,0}, o3 = {0,0,0,0};
        #pragma unroll
        for (int i = 0; i < 32; i++) {
            const float4* vp = (const float4*)(vs + (i*32 + x)*16);
            const float p = sc[i];
            float4 v0 = vp[0], v1 = vp[1], v2 = vp[2], v3 = vp[3];
            o0.x = fmaf(p, v0.x, o0.x); o0.y = fmaf(p, v0.y, o0.y);
            o0.z = fmaf(p, v0.z, o0.z); o0.w = fmaf(p, v0.w, o0.w);
            o1.x = fmaf(p, v1.x, o1.x); o1.y = fmaf(p, v1.y, o1.y);
            o1.z = fmaf(p, v1.z, o1.z); o1.w = fmaf(p, v1.w, o1.w);
            o2.x = fmaf(p, v2.x, o2.x); o2.y = fmaf(p, v2.y, o2.y);
            o2.z = fmaf(p, v2.z, o2.z); o2.w = fmaf(p, v2.w, o2.w);
            o3.x = fmaf(p, v3.x, o3.x); o3.y = fmaf(p, v3.y, o3.y);
            o3.z = fmaf(p, v3.z, o3.z); o3.w = fmaf(p, v3.w, o3.w);
        }
        acc0.x = fmaf(o0.x, inv, acc0.x); acc0.y = fmaf(o0.y, inv, acc0.y);
        acc0.z = fmaf(o0.z, inv, acc0.z); acc0.w = fmaf(o0.w, inv, acc0.w);
        acc1.x = fmaf(o1.x, inv, acc1.x); acc1.y = fmaf(o1.y, inv, acc1.y);
        acc1.z = fmaf(o1.z, inv, acc1.z); acc1.w = fmaf(o1.w, inv, acc1.w);
        acc2.x = fmaf(o2.x, inv, acc2.x); acc2.y = fmaf(o2.y, inv, acc2.y);
        acc2.z = fmaf(o2.z, inv, acc2.z); acc2.w = fmaf(o2.w, inv, acc2.w);
        acc3.x = fmaf(o3.x, inv, acc3.x); acc3.y = fmaf(o3.y, inv, acc3.y);
        acc3.z = fmaf(o3.z, inv, acc3.z); acc3.w = fmaf(o3.w, inv, acc3.w);
    }

    __syncthreads();
    float* red = asmem;
    float4* r4 = (float4*)(red + tid*20);
    r4[0] = acc0; r4[1] = acc1; r4[2] = acc2; r4[3] = acc3;
    __syncthreads();
    #pragma unroll
    for (int s = 128; s > 0; s >>= 1) {
        if (tid < s) {
            float* a_ = red + tid*20;
            const float* b_ = red + (tid + s)*20;
            #pragma unroll
            for (int d = 0; d < 16; d++) a_[d] += b_[d];
        }
        __syncthreads();
    }
    if (tid < 16) g_osum[bh*16 + tid] = red[tid];
}

// ---------------- final: tiny GEMV from partial sums ------------------------
__global__ __launch_bounds__(128) void reduce_kernel(
    const float* __restrict__ proj_w, const float* __restrict__ proj_b,
    const float* __restrict__ fc_w,   const float* __restrict__ fc_b,
    float* __restrict__ out) {
    int b = blockIdx.x, tid = threadIdx.x;
    __shared__ float meano[64], pooled[128];
    if (tid < 64) meano[tid] = g_osum[b*64 + tid] * (1.f/1024.f);
    float s = 0.f;
    #pragma unroll 4
    for (int Y = 0; Y < 32; Y++) s += g_fpart[(size_t)(b*32 + Y)*128 + tid];
    float pv = s * (1.f/1024.f) + proj_b[tid];
    __syncthreads();
    #pragma unroll 8
    for (int d = 0; d < 64; d++) pv = fmaf(proj_w[tid*64 + d], meano[d], pv);
    pooled[tid] = pv;
    __syncthreads();
    if (tid < 10) {
        float v2 = fc_b[tid];
        #pragma unroll 8
        for (int cc = 0; cc < 128; cc++) v2 = fmaf(fc_w[tid*128 + cc], pooled[cc], v2);
        out[b*10 + tid] = v2;
    }
}

// ---------------- launch ----------------------------------------------------
extern "C" void kernel_launch(void* const* d_in, const int* in_sizes, int n_in,
                              void* d_out, int out_size) {
    (void)in_sizes; (void)n_in; (void)out_size;
    const float* x       = (const float*)d_in[0];
    const float* conv1_w = (const float*)d_in[1];
    const float* conv1_b = (const float*)d_in[2];
    const float* conv2_w = (const float*)d_in[3];
    const float* conv2_b = (const float*)d_in[4];
    const float* q_w     = (const float*)d_in[5];
    const float* q_b     = (const float*)d_in[6];
    const float* k_w     = (const float*)d_in[7];
    const float* k_b     = (const float*)d_in[8];
    const float* v_w     = (const float*)d_in[9];
    const float* v_b     = (const float*)d_in[10];
    const float* proj_w  = (const float*)d_in[11];
    const float* proj_b  = (const float*)d_in[12];
    const float* rel_h   = (const float*)d_in[13];
    const float* rel_w   = (const float*)d_in[14];
    const float* fc_w    = (const float*)d_in[15];
    const float* fc_b    = (const float*)d_in[16];
    float* out = (float*)d_out;

    const int CONV2_SMEM = 25088 * 4;           // 100352 B -> 2 CTAs/SM
    const int QKV_SMEM   = (16896 + 24576) * 4; // 165888 B (staging 128x196 fits)
    const int ATTN_SMEM  = (32768 + 128) * 4;   // 131584 B
    cudaFuncSetAttribute(conv2_mma_kernel, cudaFuncAttributeMaxDynamicSharedMemorySize, CONV2_SMEM);
    cudaFuncSetAttribute(qkv_mma_kernel,  cudaFuncAttributeMaxDynamicSharedMemorySize, QKV_SMEM);
    cudaFuncSetAttribute(attn_fused_kernel, cudaFuncAttributeMaxDynamicSharedMemorySize, ATTN_SMEM);

    prep_kernel<<<434, 256>>>(conv2_w, q_w, k_w, v_w, conv1_w);
    conv1_kernel<<<dim3(16,32), 256>>>(x, conv1_w, conv1_b);
    conv2_mma_kernel<<<1024, 256, CONV2_SMEM>>>(conv2_b);
    qkv_mma_kernel<<<256, 256, QKV_SMEM>>>(q_b, k_b, v_b);
    attn_fused_kernel<<<128, 256, ATTN_SMEM>>>(rel_w, rel_h);
    reduce_kernel<<<32, 128>>>(proj_w, proj_b, fc_w, fc_b, out);
}

// round 13
// speedup vs baseline: 1.3179x; 1.3179x over previous
#include <cuda_runtime.h>
#include <cuda_fp16.h>
#include <cstdint>

// ---------------- scratch (static device globals; no allocations) ----------
__device__ __half2 g_h1h[32u*32*4356];   // conv1 out, packed ci-pairs: [b][ci2][66*66]
__device__ __half2 g_w2h[36864];         // conv2 weights, m16n8k16 fragment order (9 taps x 4096)
__device__ float g_wqkv[24576];          // qkv weights [192 x 128], fragment order (tf32)
__device__ float g_f [32u*32*32*128];    // conv2 out, NHWC, tf32-rounded values
__device__ float g_fpart[1024*128];      // per-conv2-CTA column sums of f (exact)
__device__ float g_q [32u*4*1024*16];    // [b,head,y,x,d]
__device__ float g_k [32u*4*1024*16];
__device__ float g_v [32u*4*1024*16];
__device__ float g_osum[128*16];         // per-(b,head) sum over tokens of (o_row+o_col)

// ---------------- helpers ----------------------------------------------------
__device__ __forceinline__ uint32_t smem_u32(const void* p) {
    uint32_t a;
    asm("{ .reg .u64 t; cvta.to.shared.u64 t, %1; cvt.u32.u64 %0, t; }"
        : "=r"(a) : "l"(p));
    return a;
}
__device__ __forceinline__ float tf32r(float x) {
    uint32_t u;
    asm("cvt.rna.tf32.f32 %0, %1;" : "=r"(u) : "f"(x));
    return __uint_as_float(u);
}
__device__ __forceinline__ void cpa16(uint32_t d, const void* s) {
    asm volatile("cp.async.cg.shared.global [%0], [%1], 16;" :: "r"(d), "l"(s));
}
__device__ __forceinline__ void cpa8(uint32_t d, const void* s) {
    asm volatile("cp.async.ca.shared.global [%0], [%1], 8;" :: "r"(d), "l"(s));
}
__device__ __forceinline__ void mma16n8k8(float* c, const uint32_t* a, const uint32_t* b) {
    asm volatile("mma.sync.aligned.m16n8k8.row.col.f32.tf32.tf32.f32 "
        "{%0,%1,%2,%3}, {%4,%5,%6,%7}, {%8,%9}, {%0,%1,%2,%3};"
        : "+f"(c[0]), "+f"(c[1]), "+f"(c[2]), "+f"(c[3])
        : "r"(a[0]), "r"(a[1]), "r"(a[2]), "r"(a[3]), "r"(b[0]), "r"(b[1]));
}
__device__ __forceinline__ void mma16n8k16h(float* c, const uint32_t* a, const uint32_t* b) {
    asm volatile("mma.sync.aligned.m16n8k16.row.col.f32.f16.f16.f32 "
        "{%0,%1,%2,%3}, {%4,%5,%6,%7}, {%8,%9}, {%0,%1,%2,%3};"
        : "+f"(c[0]), "+f"(c[1]), "+f"(c[2]), "+f"(c[3])
        : "r"(a[0]), "r"(a[1]), "r"(a[2]), "r"(a[3]), "r"(b[0]), "r"(b[1]));
}
__device__ __forceinline__ float dot16(float4 q0, float4 q1, float4 q2, float4 q3,
                                       const float4* kp) {
    float4 k0 = kp[0], k1 = kp[1], k2 = kp[2], k3 = kp[3];
    float s = q0.x*k0.x;
    s = fmaf(q0.y, k0.y, s); s = fmaf(q0.z, k0.z, s); s = fmaf(q0.w, k0.w, s);
    s = fmaf(q1.x, k1.x, s); s = fmaf(q1.y, k1.y, s); s = fmaf(q1.z, k1.z, s); s = fmaf(q1.w, k1.w, s);
    s = fmaf(q2.x, k2.x, s); s = fmaf(q2.y, k2.y, s); s = fmaf(q2.z, k2.z, s); s = fmaf(q2.w, k2.w, s);
    s = fmaf(q3.x, k3.x, s); s = fmaf(q3.y, k3.y, s); s = fmaf(q3.z, k3.z, s); s = fmaf(q3.w, k3.w, s);
    return s;
}

// ---------------- merged prep: w2h | wqkv | h1h border zero -----------------
// m16n8k16 B fragment: lane holds B[k][n] pairs: reg z: k0=(lane&3)*2 + z*8,
// n = lane>>2. Layout g_w2h[t][ (g*16+nf)*64 + lane*2 + z ].
__global__ __launch_bounds__(256) void prep_kernel(const float* __restrict__ w2,
                                                   const float* __restrict__ qw,
                                                   const float* __restrict__ kw,
                                                   const float* __restrict__ vw) {
    int blk = blockIdx.x, tid = threadIdx.x;
    if (blk < 144) {                       // conv2 weights -> fp16 fragment order
        int i = blk * 256 + tid;           // i < 36864
        int t = i >> 12;                   // /4096
        int r = i & 4095;
        int z = r & 1;
        int lane = (r >> 1) & 31;
        int idx = r >> 6;                  // 0..63 = g*16+nf
        int nf = idx & 15, g = idx >> 4;
        int co = nf * 8 + (lane >> 2);
        int k0 = g * 16 + (lane & 3) * 2 + z * 8;   // ci of low half
        float w0 = w2[(co * 64 + k0) * 9 + t];
        float w1v = w2[(co * 64 + k0 + 1) * 9 + t];
        g_w2h[i] = __floats2half2_rn(w0, w1v);
    } else if (blk < 240) {                // qkv weights -> tf32 fragment order
        int i = (blk - 144) * 256 + tid;
        int z = i & 1;
        int lane = (i >> 1) & 31;
        int rest = i >> 6;
        int nf = rest % 24, ks = rest / 24;
        int o = nf * 8 + (lane >> 2);
        int k = ks * 8 + (lane & 3) + 4 * z;
        float v;
        if (o < 64)       v = qw[o*128 + k] * 0.25f;
        else if (o < 128) v = kw[(o-64)*128 + k];
        else              v = vw[(o-128)*128 + k];
        g_wqkv[i] = tf32r(v);
    } else {                               // zero h1h borders (32 ci2 x 260)
        int b = blk - 240;
        __half2 zz = __floats2half2_rn(0.f, 0.f);
        for (int i = tid; i < 8320; i += 256) {
            int ci2 = i / 260, j = i % 260;
            int p, q;
            if (j < 66)       { p = 0;           q = j; }
            else if (j < 132) { p = 65;          q = j - 66; }
            else if (j < 196) { p = j - 132 + 1; q = 0; }
            else              { p = j - 196 + 1; q = 65; }
            g_h1h[((size_t)b * 32 + ci2) * 4356 + p * 66 + q] = zz;
        }
    }
}

// ---------------- conv1 scalar: conv+relu+maxpool -> packed half2 NCHW ------
__global__ __launch_bounds__(256) void conv1_kernel(const float* __restrict__ x,
                                                    const float* __restrict__ w,
                                                    const float* __restrict__ bias) {
    __shared__ float s_in[3*34*34];
    __shared__ float s_w[64*28];          // stride 28 (112B rows, 16B-aligned)
    __shared__ float s_b[64];
    int b  = blockIdx.y;
    int tY = blockIdx.x >> 2, tX = blockIdx.x & 3;
    int Py0 = tY*16, Px0 = tX*16;
    int tid = threadIdx.x;

    for (int i = tid; i < 64*27; i += 256) {
        int co = i / 27, k = i - co*27;
        s_w[co*28 + k] = w[i];
    }
    if (tid < 64) { s_b[tid] = bias[tid]; s_w[tid*28 + 27] = 0.f; }

    const float* xb = x + (size_t)b*3*128*128;
    for (int i = tid; i < 3*34*34; i += 256) {
        int ci = i / 1156, rem2 = i % 1156;
        int ly = rem2 / 34, lx = rem2 % 34;
        int gy = 2*Py0 - 1 + ly, gx = 2*Px0 - 1 + lx;
        float v = 0.f;
        if (gy >= 0 && gy < 128 && gx >= 0 && gx < 128)
            v = xb[(size_t)ci*16384 + gy*128 + gx];
        s_in[i] = v;
    }
    __syncthreads();

    int ty = tid >> 4, tx = tid & 15;
    float win[3][16];
    #pragma unroll
    for (int ci = 0; ci < 3; ci++)
        #pragma unroll
        for (int r = 0; r < 4; r++)
            #pragma unroll
            for (int c = 0; c < 4; c++)
                win[ci][r*4+c] = s_in[ci*1156 + (2*ty + r)*34 + (2*tx + c)];

    int Y = Py0 + ty, X = Px0 + tx;
    int pos = (Y + 1) * 66 + (X + 1);
    __half2* hb = g_h1h + (size_t)b * 32 * 4356 + pos;
    float prevv = 0.f;
    #pragma unroll 1
    for (int co = 0; co < 64; co++) {
        float wv[28];
        const float4* wp4 = reinterpret_cast<const float4*>(&s_w[co*28]);
        #pragma unroll
        for (int q4 = 0; q4 < 7; q4++) {
            float4 t4 = wp4[q4];
            wv[q4*4+0] = t4.x; wv[q4*4+1] = t4.y;
            wv[q4*4+2] = t4.z; wv[q4*4+3] = t4.w;
        }
        float a0=0.f, a1=0.f, a2=0.f, a3=0.f;
        #pragma unroll
        for (int ci = 0; ci < 3; ci++)
            #pragma unroll
            for (int k = 0; k < 9; k++) {
                int ky = k/3, kx = k%3;
                float wvv = wv[ci*9+k];
                a0 = fmaf(win[ci][ ky   *4 + kx    ], wvv, a0);
                a1 = fmaf(win[ci][ ky   *4 + kx + 1], wvv, a1);
                a2 = fmaf(win[ci][(ky+1)*4 + kx    ], wvv, a2);
                a3 = fmaf(win[ci][(ky+1)*4 + kx + 1], wvv, a3);
            }
        float m = fmaxf(fmaxf(a0,a1), fmaxf(a2,a3));
        float vv = fmaxf(m + s_b[co], 0.f);
        if (co & 1) hb[(size_t)(co >> 1) * 4356] = __floats2half2_rn(prevv, vv);
        else        prevv = vv;
    }
}

// ---------------- conv2 via mma.sync f16 m16n8k16 (9 taps, M=128) -----------
// slab: [ci2:32][4 rows x 66] half2, ci2-stride 264 (≡8 mod 32, conflict-free)
// B: full-tap double buffer 2x16KB. smem core 66,560B; epilogue stages
// C [128][132] f32 (67,584B) over everything. 2 CTAs/SM.
__global__ __launch_bounds__(256, 2) void conv2_mma_kernel(const float* __restrict__ b2) {
    extern __shared__ float sm[];
    __half2* h2s = (__half2*)sm;
    const int tid = threadIdx.x;
    const int lane = tid & 31, wid = tid >> 5;
    const int warp_m = wid >> 1, warp_n = wid & 1;
    const int bY = blockIdx.x;
    const int b = bY >> 5, Y = bY & 31;

    uint32_t smb = smem_u32(sm);
    const uint32_t bufBb[2] = { smb + 33792u, smb + 50176u };   // byte offsets
    const int bufBh[2] = { 8448, 12544 };                       // half2 offsets

    // prologue: slab (rows 2Y..2Y+3, 32 ci2) + tap0 (G0), tap1 (G1)
    {
        const __half2* src = g_h1h + (size_t)b * 32 * 4356 + 132 * Y;
        for (int i = tid; i < 4224; i += 256) {
            int ci2 = i / 132, j = i - ci2 * 132;
            cpa8(smb + (uint32_t)(ci2 * 264 + j * 2) * 4u,
                 src + (size_t)ci2 * 4356 + j * 2);
        }
        for (int i = tid; i < 1024; i += 256)
            cpa16(bufBb[0] + (uint32_t)i * 16u, g_w2h + i * 4);
        asm volatile("cp.async.commit_group;" ::: "memory");
        for (int i = tid; i < 1024; i += 256)
            cpa16(bufBb[1] + (uint32_t)i * 16u, g_w2h + 4096 + i * 4);
        asm volatile("cp.async.commit_group;" ::: "memory");
    }

    float c[2][8][4];
    #pragma unroll
    for (int mf = 0; mf < 2; mf++)
        #pragma unroll
        for (int nf = 0; nf < 8; nf++)
            #pragma unroll
            for (int r = 0; r < 4; r++) c[mf][nf][r] = 0.f;

    const int ry  = warp_m >> 1;
    const int xw0 = (warp_m & 1) * 32;

    #pragma unroll 1
    for (int t = 0; t < 9; t++) {
        if (t < 8) { asm volatile("cp.async.wait_group 1;" ::: "memory"); }
        else       { asm volatile("cp.async.wait_group 0;" ::: "memory"); }
        __syncthreads();

        const int ky = t / 3, kx = t - ky * 3;
        const __half2* Abase = h2s + (ry + ky) * 66 + kx + xw0 + (lane >> 2)
                             + (lane & 3) * 264;
        const __half2* Bbase = h2s + bufBh[t & 1] + warp_n * 512 + lane * 2;
        #pragma unroll
        for (int g = 0; g < 4; g++) {
            const __half2* Ak = Abase + g * 2112;          // g*8 ci2 * 264
            uint32_t a[2][4];
            #pragma unroll
            for (int mf = 0; mf < 2; mf++) {
                const __half2* Am = Ak + mf * 16;
                a[mf][0] = *reinterpret_cast<const uint32_t*>(Am);
                a[mf][1] = *reinterpret_cast<const uint32_t*>(Am + 8);
                a[mf][2] = *reinterpret_cast<const uint32_t*>(Am + 1056); // ci2+4
                a[mf][3] = *reinterpret_cast<const uint32_t*>(Am + 1064);
            }
            const __half2* Bk = Bbase + g * 1024;
            uint32_t bb[8][2];
            #pragma unroll
            for (int nf = 0; nf < 8; nf++) {
                uint2 v = *reinterpret_cast<const uint2*>(Bk + nf * 64);
                bb[nf][0] = v.x; bb[nf][1] = v.y;
            }
            #pragma unroll
            for (int mf = 0; mf < 2; mf++)
                #pragma unroll
                for (int nf = 0; nf < 8; nf++)
                    mma16n8k16h(c[mf][nf], a[mf], bb[nf]);
        }

        __syncthreads();           // done reading buf(t&1)
        if (t < 7) {               // fetch tap t+2 into freed buffer
            const __half2* wsrc = g_w2h + (t + 2) * 4096;
            uint32_t dst = bufBb[t & 1];
            for (int i = tid; i < 1024; i += 256)
                cpa16(dst + (uint32_t)i * 16u, wsrc + i * 4);
            asm volatile("cp.async.commit_group;" ::: "memory");
        }
    }

    // ---- epilogue: stage C [128][132] f32, pool+bias+relu ----
    #pragma unroll
    for (int mf = 0; mf < 2; mf++)
        #pragma unroll
        for (int nf = 0; nf < 8; nf++) {
            int m0 = warp_m*32 + mf*16 + (lane >> 2);
            int n0 = warp_n*64 + nf*8 + (lane & 3)*2;
            *reinterpret_cast<float2*>(sm + m0*132 + n0)     = make_float2(c[mf][nf][0], c[mf][nf][1]);
            *reinterpret_cast<float2*>(sm + (m0+8)*132 + n0) = make_float2(c[mf][nf][2], c[mf][nf][3]);
        }
    __syncthreads();
    float* gf = g_f + (((size_t)b*32 + Y)*32)*128;
    float fsum = 0.f;
    #pragma unroll
    for (int u = 0; u < 16; u++) {
        int idx = tid + u*256;
        int cch = idx & 127, xo = idx >> 7;
        float v0 = fmaxf(sm[(2*xo)*132 + cch],    sm[(2*xo+1)*132 + cch]);
        float v1 = fmaxf(sm[(64+2*xo)*132 + cch], sm[(64+2*xo+1)*132 + cch]);
        float v = fmaxf(fmaxf(v0, v1) + __ldg(&b2[cch]), 0.f);
        fsum += v;
        gf[(size_t)xo*128 + cch] = tf32r(v);
    }
    __syncthreads();               // staging fully consumed
    float* red = sm + 16896;       // beyond staging, within 69632B
    red[tid] = fsum;
    __syncthreads();
    if (tid < 128) g_fpart[(size_t)bY*128 + tid] = red[tid] + red[tid+128];
}

// ---------------- qkv via mma.sync tf32 (PROVEN R11: direct stores) ---------
__global__ __launch_bounds__(256) void qkv_mma_kernel(
    const float* __restrict__ qb, const float* __restrict__ kb,
    const float* __restrict__ vb) {
    extern __shared__ float sm[];
    const int tid = threadIdx.x;
    const int lane = tid & 31, wid = tid >> 5;
    const int warp_m = wid >> 1, warp_n = wid & 1;
    uint32_t smb = smem_u32(sm);

    {
        const float* gf0 = g_f + (size_t)blockIdx.x * 16384;
        for (int i = tid; i < 4096; i += 256) {
            int row = i >> 5, cg = i & 31;
            cpa16(smb + (uint32_t)(row * 132 + cg * 4) * 4u, gf0 + i * 4);
        }
        uint32_t bsb = smb + 16896u * 4u;
        for (int i = tid; i < 6144; i += 256)
            cpa16(bsb + (uint32_t)i * 16u, g_wqkv + i * 4);
        asm volatile("cp.async.commit_group;" ::: "memory");
        asm volatile("cp.async.wait_group 0;" ::: "memory");
    }
    __syncthreads();

    float c[2][12][4];
    #pragma unroll
    for (int mf = 0; mf < 2; mf++)
        #pragma unroll
        for (int nf = 0; nf < 12; nf++)
            #pragma unroll
            for (int r = 0; r < 4; r++) c[mf][nf][r] = 0.f;

    const float* Ab = sm + (warp_m * 32 + (lane >> 2)) * 132 + (lane & 3);
    const float* Bb = sm + 16896 + (warp_n * 12 * 64) + lane * 2;

    #pragma unroll 1
    for (int ks = 0; ks < 16; ks++) {
        uint32_t a[2][4];
        const float* Ak = Ab + ks * 8;
        #pragma unroll
        for (int mf = 0; mf < 2; mf++) {
            const float* Am = Ak + mf * 2112;
            a[mf][0] = __float_as_uint(Am[0]);
            a[mf][1] = __float_as_uint(Am[1056]);
            a[mf][2] = __float_as_uint(Am[4]);
            a[mf][3] = __float_as_uint(Am[1060]);
        }
        const float* Bk = Bb + ks * 1536;
        uint32_t bb[12][2];
        #pragma unroll
        for (int nf = 0; nf < 12; nf++) {
            float2 v = *reinterpret_cast<const float2*>(Bk + nf * 64);
            bb[nf][0] = __float_as_uint(v.x);
            bb[nf][1] = __float_as_uint(v.y);
        }
        #pragma unroll
        for (int mf = 0; mf < 2; mf++)
            #pragma unroll
            for (int nf = 0; nf < 12; nf++)
                mma16n8k8(c[mf][nf], a[mf], bb[nf]);
    }

    const int bb_  = blockIdx.x >> 3;
    const int rem0 = (blockIdx.x & 7) * 128 + warp_m * 32 + (lane >> 2);
    const int opair = (lane & 3) * 2;
    #pragma unroll
    for (int nf = 0; nf < 12; nf++) {
        int o = warp_n * 96 + nf * 8 + opair;
        float b0, b1; float* basep; int oo;
        if (o < 64)       { b0 = __ldg(&qb[o]) * 0.25f; b1 = __ldg(&qb[o+1]) * 0.25f; basep = g_q; oo = o; }
        else if (o < 128) { b0 = __ldg(&kb[o-64]);      b1 = __ldg(&kb[o-63]);        basep = g_k; oo = o-64; }
        else              { b0 = __ldg(&vb[o-128]);     b1 = __ldg(&vb[o-127]);       basep = g_v; oo = o-128; }
        int head = oo >> 4, d = oo & 15;
        float* hb = basep + ((size_t)(bb_ * 4 + head) * 1024) * 16 + d;
        #pragma unroll
        for (int mf = 0; mf < 2; mf++) {
            int rem = rem0 + mf * 16;
            *reinterpret_cast<float2*>(hb + (size_t)rem * 16)
                = make_float2(c[mf][nf][0] + b0, c[mf][nf][1] + b1);
            *reinterpret_cast<float2*>(hb + (size_t)(rem + 8) * 16)
                = make_float2(c[mf][nf][2] + b0, c[mf][nf][3] + b1);
        }
    }
}

// ---------------- fused axial attention (row + col), one CTA per (b,head) ---
__global__ __launch_bounds__(256) void attn_fused_kernel(const float* __restrict__ rel_w,
                                                         const float* __restrict__ rel_h) {
    extern __shared__ float asmem[];
    float* ks  = asmem;
    float* vs  = asmem + 16384;
    float* srw = asmem + 32768;
    float* srh = asmem + 32832;
    const int bh = blockIdx.x;
    const int head = bh & 3;
    const int tid = threadIdx.x;
    const int l = tid & 31, w = tid >> 5;

    {
        const float4* gk = (const float4*)(g_k + (size_t)bh * 16384);
        const float4* gv = (const float4*)(g_v + (size_t)bh * 16384);
        float4* k4 = (float4*)ks;
        float4* v4 = (float4*)vs;
        for (int i = tid; i < 4096; i += 256) { k4[i] = gk[i]; v4[i] = gv[i]; }
        if (tid < 63) { srw[tid] = rel_w[head*63 + tid]; srh[tid] = rel_h[head*63 + tid]; }
    }
    __syncthreads();

    const float* gq = g_q + (size_t)bh * 16384;
    float4 acc0 = {0,0,0,0}, acc1 = {0,0,0,0}, acc2 = {0,0,0,0}, acc3 = {0,0,0,0};

    #pragma unroll 1
    for (int u = 0; u < 4; u++) {
        const int y = w + 8*u;
        const int t = y*32 + l;
        const float4* qp = (const float4*)(gq + t*16);
        const float4 q0 = qp[0], q1 = qp[1], q2 = qp[2], q3 = qp[3];
        float sc[32];
        float mx = -1e30f;
        #pragma unroll
        for (int j = 0; j < 32; j++) {
            float s = dot16(q0, q1, q2, q3, (const float4*)(ks + (y*32 + j)*16));
            s += srw[l - j + 31];
            sc[j] = s;
            mx = fmaxf(mx, s);
        }
        float ssum = 0.f;
        #pragma unroll
        for (int j = 0; j < 32; j++) { sc[j] = __expf(sc[j] - mx); ssum += sc[j]; }
        const float inv = 1.f / ssum;
        float4 o0 = {0,0,0,0}, o1 = {0,0,0,0}, o2 = {0,0,0,0}, o3 = {0,0,0,0};
        #pragma unroll
        for (int j = 0; j < 32; j++) {
            const float4* vp = (const float4*)(vs + (y*32 + j)*16);
            const float p = sc[j];
            float4 v0 = vp[0], v1 = vp[1], v2 = vp[2], v3 = vp[3];
            o0.x = fmaf(p, v0.x, o0.x); o0.y = fmaf(p, v0.y, o0.y);
            o0.z = fmaf(p, v0.z, o0.z); o0.w = fmaf(p, v0.w, o0.w);
            o1.x = fmaf(p, v1.x, o1.x); o1.y = fmaf(p, v1.y, o1.y);
            o1.z = fmaf(p, v1.z, o1.z); o1.w = fmaf(p, v1.w, o1.w);
            o2.x = fmaf(p, v2.x, o2.x); o2.y = fmaf(p, v2.y, o2.y);
            o2.z = fmaf(p, v2.z, o2.z); o2.w = fmaf(p, v2.w, o2.w);
            o3.x = fmaf(p, v3.x, o3.x); o3.y = fmaf(p, v3.y, o3.y);
            o3.z = fmaf(p, v3.z, o3.z); o3.w = fmaf(p, v3.w, o3.w);
        }
        acc0.x = fmaf(o0.x, inv, acc0.x); acc0.y = fmaf(o0.y, inv, acc0.y);
        acc0.z = fmaf(o0.z, inv, acc0.z); acc0.w = fmaf(o0.w, inv, acc0.w);
        acc1.x = fmaf(o1.x, inv, acc1.x); acc1.y = fmaf(o1.y, inv, acc1.y);
        acc1.z = fmaf(o1.z, inv, acc1.z); acc1.w = fmaf(o1.w, inv, acc1.w);
        acc2.x = fmaf(o2.x, inv, acc2.x); acc2.y = fmaf(o2.y, inv, acc2.y);
        acc2.z = fmaf(o2.z, inv, acc2.z); acc2.w = fmaf(o2.w, inv, acc2.w);
        acc3.x = fmaf(o3.x, inv, acc3.x); acc3.y = fmaf(o3.y, inv, acc3.y);
        acc3.z = fmaf(o3.z, inv, acc3.z); acc3.w = fmaf(o3.w, inv, acc3.w);
    }

    #pragma unroll 1
    for (int u = 0; u < 4; u++) {
        const int x = w + 8*u;
        const int t = l*32 + x;
        const float4* qp = (const float4*)(gq + t*16);
        const float4 q0 = qp[0], q1 = qp[1], q2 = qp[2], q3 = qp[3];
        float sc[32];
        float mx = -1e30f;
        #pragma unroll
        for (int i = 0; i < 32; i++) {
            float s = dot16(q0, q1, q2, q3, (const float4*)(ks + (i*32 + x)*16));
            s += srh[l - i + 31];
            sc[i] = s;
            mx = fmaxf(mx, s);
        }
        float ssum = 0.f;
        #pragma unroll
        for (int i = 0; i < 32; i++) { sc[i] = __expf(sc[i] - mx); ssum += sc[i]; }
        const float inv = 1.f / ssum;
        float4 o0 = {0,0,0,0}, o1 = {0,0,0,0}, o2 = {0,0,0,0}, o3 = {0,0,0,0};
        #pragma unroll
        for (int i = 0; i < 32; i++) {
            const float4* vp = (const float4*)(vs + (i*32 + x)*16);
            const float p = sc[i];
            float4 v0 = vp[0], v1 = vp[1], v2 = vp[2], v3 = vp[3];
            o0.x = fmaf(p, v0.x, o0.x); o0.y = fmaf(p, v0.y, o0.y);
            o0.z = fmaf(p, v0.z, o0.z); o0.w = fmaf(p, v0.w, o0.w);
            o1.x = fmaf(p, v1.x, o1.x); o1.y = fmaf(p, v1.y, o1.y);
            o1.z = fmaf(p, v1.z, o1.z); o1.w = fmaf(p, v1.w, o1.w);
            o2.x = fmaf(p, v2.x, o2.x); o2.y = fmaf(p, v2.y, o2.y);
            o2.z = fmaf(p, v2.z, o2.z); o2.w = fmaf(p, v2.w, o2.w);
            o3.x = fmaf(p, v3.x, o3.x); o3.y = fmaf(p, v3.y, o3.y);
            o3.z = fmaf(p, v3.z, o3.z); o3.w = fmaf(p, v3.w, o3.w);
        }
        acc0.x = fmaf(o0.x, inv, acc0.x); acc0.y = fmaf(o0.y, inv, acc0.y);
        acc0.z = fmaf(o0.z, inv, acc0.z); acc0.w = fmaf(o0.w, inv, acc0.w);
        acc1.x = fmaf(o1.x, inv, acc1.x); acc1.y = fmaf(o1.y, inv, acc1.y);
        acc1.z = fmaf(o1.z, inv, acc1.z); acc1.w = fmaf(o1.w, inv, acc1.w);
        acc2.x = fmaf(o2.x, inv, acc2.x); acc2.y = fmaf(o2.y, inv, acc2.y);
        acc2.z = fmaf(o2.z, inv, acc2.z); acc2.w = fmaf(o2.w, inv, acc2.w);
        acc3.x = fmaf(o3.x, inv, acc3.x); acc3.y = fmaf(o3.y, inv, acc3.y);
        acc3.z = fmaf(o3.z, inv, acc3.z); acc3.w = fmaf(o3.w, inv, acc3.w);
    }

    __syncthreads();
    float* red = asmem;
    float4* r4 = (float4*)(red + tid*20);
    r4[0] = acc0; r4[1] = acc1; r4[2] = acc2; r4[3] = acc3;
    __syncthreads();
    #pragma unroll
    for (int s = 128; s > 0; s >>= 1) {
        if (tid < s) {
            float* a_ = red + tid*20;
            const float* b_ = red + (tid + s)*20;
            #pragma unroll
            for (int d = 0; d < 16; d++) a_[d] += b_[d];
        }
        __syncthreads();
    }
    if (tid < 16) g_osum[bh*16 + tid] = red[tid];
}

// ---------------- final: tiny GEMV from partial sums ------------------------
__global__ __launch_bounds__(128) void reduce_kernel(
    const float* __restrict__ proj_w, const float* __restrict__ proj_b,
    const float* __restrict__ fc_w,   const float* __restrict__ fc_b,
    float* __restrict__ out) {
    int b = blockIdx.x, tid = threadIdx.x;
    __shared__ float meano[64], pooled[128];
    if (tid < 64) meano[tid] = g_osum[b*64 + tid] * (1.f/1024.f);
    float s = 0.f;
    #pragma unroll 4
    for (int Y = 0; Y < 32; Y++) s += g_fpart[(size_t)(b*32 + Y)*128 + tid];
    float pv = s * (1.f/1024.f) + proj_b[tid];
    __syncthreads();
    #pragma unroll 8
    for (int d = 0; d < 64; d++) pv = fmaf(proj_w[tid*64 + d], meano[d], pv);
    pooled[tid] = pv;
    __syncthreads();
    if (tid < 10) {
        float v2 = fc_b[tid];
        #pragma unroll 8
        for (int cc = 0; cc < 128; cc++) v2 = fmaf(fc_w[tid*128 + cc], pooled[cc], v2);
        out[b*10 + tid] = v2;
    }
}

// ---------------- launch ----------------------------------------------------
extern "C" void kernel_launch(void* const* d_in, const int* in_sizes, int n_in,
                              void* d_out, int out_size) {
    (void)in_sizes; (void)n_in; (void)out_size;
    const float* x       = (const float*)d_in[0];
    const float* conv1_w = (const float*)d_in[1];
    const float* conv1_b = (const float*)d_in[2];
    const float* conv2_w = (const float*)d_in[3];
    const float* conv2_b = (const float*)d_in[4];
    const float* q_w     = (const float*)d_in[5];
    const float* q_b     = (const float*)d_in[6];
    const float* k_w     = (const float*)d_in[7];
    const float* k_b     = (const float*)d_in[8];
    const float* v_w     = (const float*)d_in[9];
    const float* v_b     = (const float*)d_in[10];
    const float* proj_w  = (const float*)d_in[11];
    const float* proj_b  = (const float*)d_in[12];
    const float* rel_h   = (const float*)d_in[13];
    const float* rel_w   = (const float*)d_in[14];
    const float* fc_w    = (const float*)d_in[15];
    const float* fc_b    = (const float*)d_in[16];
    float* out = (float*)d_out;

    const int CONV2_SMEM = 69632;               // core 66560B, epilogue 67584B
    const int QKV_SMEM   = (16896 + 24576) * 4; // 165888 B
    const int ATTN_SMEM  = (32768 + 128) * 4;   // 131584 B
    cudaFuncSetAttribute(conv2_mma_kernel, cudaFuncAttributeMaxDynamicSharedMemorySize, CONV2_SMEM);
    cudaFuncSetAttribute(qkv_mma_kernel,  cudaFuncAttributeMaxDynamicSharedMemorySize, QKV_SMEM);
    cudaFuncSetAttribute(attn_fused_kernel, cudaFuncAttributeMaxDynamicSharedMemorySize, ATTN_SMEM);

    prep_kernel<<<272, 256>>>(conv2_w, q_w, k_w, v_w);
    conv1_kernel<<<dim3(16,32), 256>>>(x, conv1_w, conv1_b);
    conv2_mma_kernel<<<1024, 256, CONV2_SMEM>>>(conv2_b);
    qkv_mma_kernel<<<256, 256, QKV_SMEM>>>(q_b, k_b, v_b);
    attn_fused_kernel<<<128, 256, ATTN_SMEM>>>(rel_w, rel_h);
    reduce_kernel<<<32, 128>>>(proj_w, proj_b, fc_w, fc_b, out);
}

// round 14
// speedup vs baseline: 1.3965x; 1.0597x over previous
#include <cuda_runtime.h>
#include <cuda_fp16.h>
#include <cstdint>

// ---------------- scratch (static device globals; no allocations) ----------
__device__ __half2 g_h1h[32u*32*4356];   // conv1 out, packed ci-pairs: [b][ci2][66*66]
__device__ __half2 g_w2h[36864];         // conv2 weights, m16n8k16 fragment order (9 taps x 4096)
__device__ float g_wqkv[24576];          // qkv weights [192 x 128], fragment order (tf32)
__device__ float g_f [32u*32*32*128];    // conv2 out, NHWC, tf32-rounded values
__device__ float g_fpart[1024*128];      // per-conv2-CTA column sums of f (exact)
__device__ float g_q [32u*4*1024*16];    // [b,head,y,x,d]
__device__ float g_k [32u*4*1024*16];
__device__ float g_v [32u*4*1024*16];
__device__ float g_osum[128*16];         // per-(b,head) sum over tokens of (o_row+o_col)

// ---------------- helpers ----------------------------------------------------
__device__ __forceinline__ uint32_t smem_u32(const void* p) {
    uint32_t a;
    asm("{ .reg .u64 t; cvta.to.shared.u64 t, %1; cvt.u32.u64 %0, t; }"
        : "=r"(a) : "l"(p));
    return a;
}
__device__ __forceinline__ float tf32r(float x) {
    uint32_t u;
    asm("cvt.rna.tf32.f32 %0, %1;" : "=r"(u) : "f"(x));
    return __uint_as_float(u);
}
__device__ __forceinline__ void cpa16(uint32_t d, const void* s) {
    asm volatile("cp.async.cg.shared.global [%0], [%1], 16;" :: "r"(d), "l"(s));
}
__device__ __forceinline__ void cpa8(uint32_t d, const void* s) {
    asm volatile("cp.async.ca.shared.global [%0], [%1], 8;" :: "r"(d), "l"(s));
}
__device__ __forceinline__ void mma16n8k8(float* c, const uint32_t* a, const uint32_t* b) {
    asm volatile("mma.sync.aligned.m16n8k8.row.col.f32.tf32.tf32.f32 "
        "{%0,%1,%2,%3}, {%4,%5,%6,%7}, {%8,%9}, {%0,%1,%2,%3};"
        : "+f"(c[0]), "+f"(c[1]), "+f"(c[2]), "+f"(c[3])
        : "r"(a[0]), "r"(a[1]), "r"(a[2]), "r"(a[3]), "r"(b[0]), "r"(b[1]));
}
__device__ __forceinline__ void mma16n8k16h(float* c, const uint32_t* a, const uint32_t* b) {
    asm volatile("mma.sync.aligned.m16n8k16.row.col.f32.f16.f16.f32 "
        "{%0,%1,%2,%3}, {%4,%5,%6,%7}, {%8,%9}, {%0,%1,%2,%3};"
        : "+f"(c[0]), "+f"(c[1]), "+f"(c[2]), "+f"(c[3])
        : "r"(a[0]), "r"(a[1]), "r"(a[2]), "r"(a[3]), "r"(b[0]), "r"(b[1]));
}
__device__ __forceinline__ float dot16(float4 q0, float4 q1, float4 q2, float4 q3,
                                       const float4* kp) {
    float4 k0 = kp[0], k1 = kp[1], k2 = kp[2], k3 = kp[3];
    float s = q0.x*k0.x;
    s = fmaf(q0.y, k0.y, s); s = fmaf(q0.z, k0.z, s); s = fmaf(q0.w, k0.w, s);
    s = fmaf(q1.x, k1.x, s); s = fmaf(q1.y, k1.y, s); s = fmaf(q1.z, k1.z, s); s = fmaf(q1.w, k1.w, s);
    s = fmaf(q2.x, k2.x, s); s = fmaf(q2.y, k2.y, s); s = fmaf(q2.z, k2.z, s); s = fmaf(q2.w, k2.w, s);
    s = fmaf(q3.x, k3.x, s); s = fmaf(q3.y, k3.y, s); s = fmaf(q3.z, k3.z, s); s = fmaf(q3.w, k3.w, s);
    return s;
}

// ---------------- merged prep: w2h | wqkv | h1h border zero -----------------
__global__ __launch_bounds__(256) void prep_kernel(const float* __restrict__ w2,
                                                   const float* __restrict__ qw,
                                                   const float* __restrict__ kw,
                                                   const float* __restrict__ vw) {
    int blk = blockIdx.x, tid = threadIdx.x;
    if (blk < 144) {                       // conv2 weights -> fp16 fragment order
        int i = blk * 256 + tid;           // i < 36864
        int t = i >> 12;                   // /4096
        int r = i & 4095;
        int z = r & 1;
        int lane = (r >> 1) & 31;
        int idx = r >> 6;                  // 0..63 = g*16+nf
        int nf = idx & 15, g = idx >> 4;
        int co = nf * 8 + (lane >> 2);
        int k0 = g * 16 + (lane & 3) * 2 + z * 8;
        float w0 = w2[(co * 64 + k0) * 9 + t];
        float w1v = w2[(co * 64 + k0 + 1) * 9 + t];
        g_w2h[i] = __floats2half2_rn(w0, w1v);
    } else if (blk < 240) {                // qkv weights -> tf32 fragment order
        int i = (blk - 144) * 256 + tid;
        int z = i & 1;
        int lane = (i >> 1) & 31;
        int rest = i >> 6;
        int nf = rest % 24, ks = rest / 24;
        int o = nf * 8 + (lane >> 2);
        int k = ks * 8 + (lane & 3) + 4 * z;
        float v;
        if (o < 64)       v = qw[o*128 + k] * 0.25f;
        else if (o < 128) v = kw[(o-64)*128 + k];
        else              v = vw[(o-128)*128 + k];
        g_wqkv[i] = tf32r(v);
    } else {                               // zero h1h borders (32 ci2 x 260)
        int b = blk - 240;
        __half2 zz = __floats2half2_rn(0.f, 0.f);
        for (int i = tid; i < 8320; i += 256) {
            int ci2 = i / 260, j = i % 260;
            int p, q;
            if (j < 66)       { p = 0;           q = j; }
            else if (j < 132) { p = 65;          q = j - 66; }
            else if (j < 196) { p = j - 132 + 1; q = 0; }
            else              { p = j - 196 + 1; q = 65; }
            g_h1h[((size_t)b * 32 + ci2) * 4356 + p * 66 + q] = zz;
        }
    }
}

// ---------------- conv1 scalar, 2 pooled outputs/thread (8 FMA per weight) --
// Block tile: 32 pooled x X 16 pooled y. Thread: (ty, tx2) -> outputs
// (Y=Py0+ty, X=Px0+2*tx2 + {0,1}) for all 64 co. Packed half2 NCHW out.
__global__ __launch_bounds__(256, 2) void conv1_kernel(const float* __restrict__ x,
                                                       const float* __restrict__ w,
                                                       const float* __restrict__ bias) {
    __shared__ float s_in[3*34*66];       // 6732
    __shared__ float s_w[64*28];          // stride 28 (112B rows, 16B-aligned)
    __shared__ float s_b[64];
    int b  = blockIdx.y;
    int tY = blockIdx.x >> 1, tX = blockIdx.x & 1;
    int Py0 = tY*16, Px0 = tX*32;
    int tid = threadIdx.x;

    for (int i = tid; i < 64*27; i += 256) {
        int co = i / 27, k = i - co*27;
        s_w[co*28 + k] = w[i];
    }
    if (tid < 64) { s_b[tid] = bias[tid]; s_w[tid*28 + 27] = 0.f; }

    const float* xb = x + (size_t)b*3*128*128;
    for (int i = tid; i < 3*34*66; i += 256) {
        int ci = i / 2244, rem2 = i % 2244;
        int ly = rem2 / 66, lx = rem2 % 66;
        int gy = 2*Py0 - 1 + ly, gx = 2*Px0 - 1 + lx;
        float v = 0.f;
        if (gy >= 0 && gy < 128 && gx >= 0 && gx < 128)
            v = xb[(size_t)ci*16384 + gy*128 + gx];
        s_in[i] = v;
    }
    __syncthreads();

    int ty = tid >> 4, tx2 = tid & 15;
    float win[3][24];                     // [ci][r*6 + c], r in 0..3, c in 0..5
    #pragma unroll
    for (int ci = 0; ci < 3; ci++)
        #pragma unroll
        for (int r = 0; r < 4; r++)
            #pragma unroll
            for (int c = 0; c < 6; c++)
                win[ci][r*6+c] = s_in[ci*2244 + (2*ty + r)*66 + (4*tx2 + c)];

    int Y = Py0 + ty;
    int X0 = Px0 + 2*tx2;
    int pos0 = (Y + 1) * 66 + (X0 + 1);   // output p at pos0 + p
    __half2* hb = g_h1h + (size_t)b * 32 * 4356;
    float prev[2];
    #pragma unroll 1
    for (int co = 0; co < 64; co++) {
        float wv[28];
        const float4* wp4 = reinterpret_cast<const float4*>(&s_w[co*28]);
        #pragma unroll
        for (int q4 = 0; q4 < 7; q4++) {
            float4 t4 = wp4[q4];
            wv[q4*4+0] = t4.x; wv[q4*4+1] = t4.y;
            wv[q4*4+2] = t4.z; wv[q4*4+3] = t4.w;
        }
        float a0[4] = {0.f,0.f,0.f,0.f};  // output p=0: dy*2+dx
        float a1[4] = {0.f,0.f,0.f,0.f};  // output p=1
        #pragma unroll
        for (int ci = 0; ci < 3; ci++)
            #pragma unroll
            for (int k = 0; k < 9; k++) {
                int ky = k/3, kx = k%3;
                float wvv = wv[ci*9+k];
                const float* wr0 = &win[ci][ ky   *6 + kx];
                const float* wr1 = &win[ci][(ky+1)*6 + kx];
                a0[0] = fmaf(wr0[0], wvv, a0[0]);
                a0[1] = fmaf(wr0[1], wvv, a0[1]);
                a0[2] = fmaf(wr1[0], wvv, a0[2]);
                a0[3] = fmaf(wr1[1], wvv, a0[3]);
                a1[0] = fmaf(wr0[2], wvv, a1[0]);
                a1[1] = fmaf(wr0[3], wvv, a1[1]);
                a1[2] = fmaf(wr1[2], wvv, a1[2]);
                a1[3] = fmaf(wr1[3], wvv, a1[3]);
            }
        float m0 = fmaxf(fmaxf(a0[0],a0[1]), fmaxf(a0[2],a0[3]));
        float m1 = fmaxf(fmaxf(a1[0],a1[1]), fmaxf(a1[2],a1[3]));
        float v0 = fmaxf(m0 + s_b[co], 0.f);
        float v1 = fmaxf(m1 + s_b[co], 0.f);
        if (co & 1) {
            __half2* dst = hb + (size_t)(co >> 1) * 4356 + pos0;
            dst[0] = __floats2half2_rn(prev[0], v0);
            dst[1] = __floats2half2_rn(prev[1], v1);
        } else {
            prev[0] = v0; prev[1] = v1;
        }
    }
}

// ---------------- conv2 via mma.sync f16 m16n8k16 (9 taps, M=128) -----------
__global__ __launch_bounds__(256, 2) void conv2_mma_kernel(const float* __restrict__ b2) {
    extern __shared__ float sm[];
    __half2* h2s = (__half2*)sm;
    const int tid = threadIdx.x;
    const int lane = tid & 31, wid = tid >> 5;
    const int warp_m = wid >> 1, warp_n = wid & 1;
    const int bY = blockIdx.x;
    const int b = bY >> 5, Y = bY & 31;

    uint32_t smb = smem_u32(sm);
    const uint32_t bufBb[2] = { smb + 33792u, smb + 50176u };
    const int bufBh[2] = { 8448, 12544 };

    {
        const __half2* src = g_h1h + (size_t)b * 32 * 4356 + 132 * Y;
        for (int i = tid; i < 4224; i += 256) {
            int ci2 = i / 132, j = i - ci2 * 132;
            cpa8(smb + (uint32_t)(ci2 * 264 + j * 2) * 4u,
                 src + (size_t)ci2 * 4356 + j * 2);
        }
        for (int i = tid; i < 1024; i += 256)
            cpa16(bufBb[0] + (uint32_t)i * 16u, g_w2h + i * 4);
        asm volatile("cp.async.commit_group;" ::: "memory");
        for (int i = tid; i < 1024; i += 256)
            cpa16(bufBb[1] + (uint32_t)i * 16u, g_w2h + 4096 + i * 4);
        asm volatile("cp.async.commit_group;" ::: "memory");
    }

    float c[2][8][4];
    #pragma unroll
    for (int mf = 0; mf < 2; mf++)
        #pragma unroll
        for (int nf = 0; nf < 8; nf++)
            #pragma unroll
            for (int r = 0; r < 4; r++) c[mf][nf][r] = 0.f;

    const int ry  = warp_m >> 1;
    const int xw0 = (warp_m & 1) * 32;

    #pragma unroll 1
    for (int t = 0; t < 9; t++) {
        if (t < 8) { asm volatile("cp.async.wait_group 1;" ::: "memory"); }
        else       { asm volatile("cp.async.wait_group 0;" ::: "memory"); }
        __syncthreads();

        const int ky = t / 3, kx = t - ky * 3;
        const __half2* Abase = h2s + (ry + ky) * 66 + kx + xw0 + (lane >> 2)
                             + (lane & 3) * 264;
        const __half2* Bbase = h2s + bufBh[t & 1] + warp_n * 512 + lane * 2;
        #pragma unroll
        for (int g = 0; g < 4; g++) {
            const __half2* Ak = Abase + g * 2112;
            uint32_t a[2][4];
            #pragma unroll
            for (int mf = 0; mf < 2; mf++) {
                const __half2* Am = Ak + mf * 16;
                a[mf][0] = *reinterpret_cast<const uint32_t*>(Am);
                a[mf][1] = *reinterpret_cast<const uint32_t*>(Am + 8);
                a[mf][2] = *reinterpret_cast<const uint32_t*>(Am + 1056);
                a[mf][3] = *reinterpret_cast<const uint32_t*>(Am + 1064);
            }
            const __half2* Bk = Bbase + g * 1024;
            uint32_t bb[8][2];
            #pragma unroll
            for (int nf = 0; nf < 8; nf++) {
                uint2 v = *reinterpret_cast<const uint2*>(Bk + nf * 64);
                bb[nf][0] = v.x; bb[nf][1] = v.y;
            }
            #pragma unroll
            for (int mf = 0; mf < 2; mf++)
                #pragma unroll
                for (int nf = 0; nf < 8; nf++)
                    mma16n8k16h(c[mf][nf], a[mf], bb[nf]);
        }

        __syncthreads();
        if (t < 7) {
            const __half2* wsrc = g_w2h + (t + 2) * 4096;
            uint32_t dst = bufBb[t & 1];
            for (int i = tid; i < 1024; i += 256)
                cpa16(dst + (uint32_t)i * 16u, wsrc + i * 4);
            asm volatile("cp.async.commit_group;" ::: "memory");
        }
    }

    // ---- epilogue: stage C [128][132] f32, pool+bias+relu ----
    #pragma unroll
    for (int mf = 0; mf < 2; mf++)
        #pragma unroll
        for (int nf = 0; nf < 8; nf++) {
            int m0 = warp_m*32 + mf*16 + (lane >> 2);
            int n0 = warp_n*64 + nf*8 + (lane & 3)*2;
            *reinterpret_cast<float2*>(sm + m0*132 + n0)     = make_float2(c[mf][nf][0], c[mf][nf][1]);
            *reinterpret_cast<float2*>(sm + (m0+8)*132 + n0) = make_float2(c[mf][nf][2], c[mf][nf][3]);
        }
    __syncthreads();
    float* gf = g_f + (((size_t)b*32 + Y)*32)*128;
    float fsum = 0.f;
    #pragma unroll
    for (int u = 0; u < 16; u++) {
        int idx = tid + u*256;
        int cch = idx & 127, xo = idx >> 7;
        float v0 = fmaxf(sm[(2*xo)*132 + cch],    sm[(2*xo+1)*132 + cch]);
        float v1 = fmaxf(sm[(64+2*xo)*132 + cch], sm[(64+2*xo+1)*132 + cch]);
        float v = fmaxf(fmaxf(v0, v1) + __ldg(&b2[cch]), 0.f);
        fsum += v;
        gf[(size_t)xo*128 + cch] = tf32r(v);
    }
    __syncthreads();
    float* red = sm + 16896;
    red[tid] = fsum;
    __syncthreads();
    if (tid < 128) g_fpart[(size_t)bY*128 + tid] = red[tid] + red[tid+128];
}

// ---------------- qkv via mma.sync tf32 (PROVEN R11: direct stores) ---------
__global__ __launch_bounds__(256) void qkv_mma_kernel(
    const float* __restrict__ qb, const float* __restrict__ kb,
    const float* __restrict__ vb) {
    extern __shared__ float sm[];
    const int tid = threadIdx.x;
    const int lane = tid & 31, wid = tid >> 5;
    const int warp_m = wid >> 1, warp_n = wid & 1;
    uint32_t smb = smem_u32(sm);

    {
        const float* gf0 = g_f + (size_t)blockIdx.x * 16384;
        for (int i = tid; i < 4096; i += 256) {
            int row = i >> 5, cg = i & 31;
            cpa16(smb + (uint32_t)(row * 132 + cg * 4) * 4u, gf0 + i * 4);
        }
        uint32_t bsb = smb + 16896u * 4u;
        for (int i = tid; i < 6144; i += 256)
            cpa16(bsb + (uint32_t)i * 16u, g_wqkv + i * 4);
        asm volatile("cp.async.commit_group;" ::: "memory");
        asm volatile("cp.async.wait_group 0;" ::: "memory");
    }
    __syncthreads();

    float c[2][12][4];
    #pragma unroll
    for (int mf = 0; mf < 2; mf++)
        #pragma unroll
        for (int nf = 0; nf < 12; nf++)
            #pragma unroll
            for (int r = 0; r < 4; r++) c[mf][nf][r] = 0.f;

    const float* Ab = sm + (warp_m * 32 + (lane >> 2)) * 132 + (lane & 3);
    const float* Bb = sm + 16896 + (warp_n * 12 * 64) + lane * 2;

    #pragma unroll 1
    for (int ks = 0; ks < 16; ks++) {
        uint32_t a[2][4];
        const float* Ak = Ab + ks * 8;
        #pragma unroll
        for (int mf = 0; mf < 2; mf++) {
            const float* Am = Ak + mf * 2112;
            a[mf][0] = __float_as_uint(Am[0]);
            a[mf][1] = __float_as_uint(Am[1056]);
            a[mf][2] = __float_as_uint(Am[4]);
            a[mf][3] = __float_as_uint(Am[1060]);
        }
        const float* Bk = Bb + ks * 1536;
        uint32_t bb[12][2];
        #pragma unroll
        for (int nf = 0; nf < 12; nf++) {
            float2 v = *reinterpret_cast<const float2*>(Bk + nf * 64);
            bb[nf][0] = __float_as_uint(v.x);
            bb[nf][1] = __float_as_uint(v.y);
        }
        #pragma unroll
        for (int mf = 0; mf < 2; mf++)
            #pragma unroll
            for (int nf = 0; nf < 12; nf++)
                mma16n8k8(c[mf][nf], a[mf], bb[nf]);
    }

    const int bb_  = blockIdx.x >> 3;
    const int rem0 = (blockIdx.x & 7) * 128 + warp_m * 32 + (lane >> 2);
    const int opair = (lane & 3) * 2;
    #pragma unroll
    for (int nf = 0; nf < 12; nf++) {
        int o = warp_n * 96 + nf * 8 + opair;
        float b0, b1; float* basep; int oo;
        if (o < 64)       { b0 = __ldg(&qb[o]) * 0.25f; b1 = __ldg(&qb[o+1]) * 0.25f; basep = g_q; oo = o; }
        else if (o < 128) { b0 = __ldg(&kb[o-64]);      b1 = __ldg(&kb[o-63]);        basep = g_k; oo = o-64; }
        else              { b0 = __ldg(&vb[o-128]);     b1 = __ldg(&vb[o-127]);       basep = g_v; oo = o-128; }
        int head = oo >> 4, d = oo & 15;
        float* hb = basep + ((size_t)(bb_ * 4 + head) * 1024) * 16 + d;
        #pragma unroll
        for (int mf = 0; mf < 2; mf++) {
            int rem = rem0 + mf * 16;
            *reinterpret_cast<float2*>(hb + (size_t)rem * 16)
                = make_float2(c[mf][nf][0] + b0, c[mf][nf][1] + b1);
            *reinterpret_cast<float2*>(hb + (size_t)(rem + 8) * 16)
                = make_float2(c[mf][nf][2] + b0, c[mf][nf][3] + b1);
        }
    }
}

// ---------------- fused axial attention (row + col), one CTA per (b,head) ---
__global__ __launch_bounds__(256) void attn_fused_kernel(const float* __restrict__ rel_w,
                                                         const float* __restrict__ rel_h) {
    extern __shared__ float asmem[];
    float* ks  = asmem;
    float* vs  = asmem + 16384;
    float* srw = asmem + 32768;
    float* srh = asmem + 32832;
    const int bh = blockIdx.x;
    const int head = bh & 3;
    const int tid = threadIdx.x;
    const int l = tid & 31, w = tid >> 5;

    {
        const float4* gk = (const float4*)(g_k + (size_t)bh * 16384);
        const float4* gv = (const float4*)(g_v + (size_t)bh * 16384);
        float4* k4 = (float4*)ks;
        float4* v4 = (float4*)vs;
        for (int i = tid; i < 4096; i += 256) { k4[i] = gk[i]; v4[i] = gv[i]; }
        if (tid < 63) { srw[tid] = rel_w[head*63 + tid]; srh[tid] = rel_h[head*63 + tid]; }
    }
    __syncthreads();

    const float* gq = g_q + (size_t)bh * 16384;
    float4 acc0 = {0,0,0,0}, acc1 = {0,0,0,0}, acc2 = {0,0,0,0}, acc3 = {0,0,0,0};

    #pragma unroll 1
    for (int u = 0; u < 4; u++) {
        const int y = w + 8*u;
        const int t = y*32 + l;
        const float4* qp = (const float4*)(gq + t*16);
        const float4 q0 = qp[0], q1 = qp[1], q2 = qp[2], q3 = qp[3];
        float sc[32];
        float mx = -1e30f;
        #pragma unroll
        for (int j = 0; j < 32; j++) {
            float s = dot16(q0, q1, q2, q3, (const float4*)(ks + (y*32 + j)*16));
            s += srw[l - j + 31];
            sc[j] = s;
            mx = fmaxf(mx, s);
        }
        float ssum = 0.f;
        #pragma unroll
        for (int j = 0; j < 32; j++) { sc[j] = __expf(sc[j] - mx); ssum += sc[j]; }
        const float inv = 1.f / ssum;
        float4 o0 = {0,0,0,0}, o1 = {0,0,0,0}, o2 = {0,0,0,0}, o3 = {0,0,0,0};
        #pragma unroll
        for (int j = 0; j < 32; j++) {
            const float4* vp = (const float4*)(vs + (y*32 + j)*16);
            const float p = sc[j];
            float4 v0 = vp[0], v1 = vp[1], v2 = vp[2], v3 = vp[3];
            o0.x = fmaf(p, v0.x, o0.x); o0.y = fmaf(p, v0.y, o0.y);
            o0.z = fmaf(p, v0.z, o0.z); o0.w = fmaf(p, v0.w, o0.w);
            o1.x = fmaf(p, v1.x, o1.x); o1.y = fmaf(p, v1.y, o1.y);
            o1.z = fmaf(p, v1.z, o1.z); o1.w = fmaf(p, v1.w, o1.w);
            o2.x = fmaf(p, v2.x, o2.x); o2.y = fmaf(p, v2.y, o2.y);
            o2.z = fmaf(p, v2.z, o2.z); o2.w = fmaf(p, v2.w, o2.w);
            o3.x = fmaf(p, v3.x, o3.x); o3.y = fmaf(p, v3.y, o3.y);
            o3.z = fmaf(p, v3.z, o3.z); o3.w = fmaf(p, v3.w, o3.w);
        }
        acc0.x = fmaf(o0.x, inv, acc0.x); acc0.y = fmaf(o0.y, inv, acc0.y);
        acc0.z = fmaf(o0.z, inv, acc0.z); acc0.w = fmaf(o0.w, inv, acc0.w);
        acc1.x = fmaf(o1.x, inv, acc1.x); acc1.y = fmaf(o1.y, inv, acc1.y);
        acc1.z = fmaf(o1.z, inv, acc1.z); acc1.w = fmaf(o1.w, inv, acc1.w);
        acc2.x = fmaf(o2.x, inv, acc2.x); acc2.y = fmaf(o2.y, inv, acc2.y);
        acc2.z = fmaf(o2.z, inv, acc2.z); acc2.w = fmaf(o2.w, inv, acc2.w);
        acc3.x = fmaf(o3.x, inv, acc3.x); acc3.y = fmaf(o3.y, inv, acc3.y);
        acc3.z = fmaf(o3.z, inv, acc3.z); acc3.w = fmaf(o3.w, inv, acc3.w);
    }

    #pragma unroll 1
    for (int u = 0; u < 4; u++) {
        const int x = w + 8*u;
        const int t = l*32 + x;
        const float4* qp = (const float4*)(gq + t*16);
        const float4 q0 = qp[0], q1 = qp[1], q2 = qp[2], q3 = qp[3];
        float sc[32];
        float mx = -1e30f;
        #pragma unroll
        for (int i = 0; i < 32; i++) {
            float s = dot16(q0, q1, q2, q3, (const float4*)(ks + (i*32 + x)*16));
            s += srh[l - i + 31];
            sc[i] = s;
            mx = fmaxf(mx, s);
        }
        float ssum = 0.f;
        #pragma unroll
        for (int i = 0; i < 32; i++) { sc[i] = __expf(sc[i] - mx); ssum += sc[i]; }
        const float inv = 1.f / ssum;
        float4 o0 = {0,0,0,0}, o1 = {0,0,0,0}, o2 = {0,0,0,0}, o3 = {0,0,0,0};
        #pragma unroll
        for (int i = 0; i < 32; i++) {
            const float4* vp = (const float4*)(vs + (i*32 + x)*16);
            const float p = sc[i];
            float4 v0 = vp[0], v1 = vp[1], v2 = vp[2], v3 = vp[3];
            o0.x = fmaf(p, v0.x, o0.x); o0.y = fmaf(p, v0.y, o0.y);
            o0.z = fmaf(p, v0.z, o0.z); o0.w = fmaf(p, v0.w, o0.w);
            o1.x = fmaf(p, v1.x, o1.x); o1.y = fmaf(p, v1.y, o1.y);
            o1.z = fmaf(p, v1.z, o1.z); o1.w = fmaf(p, v1.w, o1.w);
            o2.x = fmaf(p, v2.x, o2.x); o2.y = fmaf(p, v2.y, o2.y);
            o2.z = fmaf(p, v2.z, o2.z); o2.w = fmaf(p, v2.w, o2.w);
            o3.x = fmaf(p, v3.x, o3.x); o3.y = fmaf(p, v3.y, o3.y);
            o3.z = fmaf(p, v3.z, o3.z); o3.w = fmaf(p, v3.w, o3.w);
        }
        acc0.x = fmaf(o0.x, inv, acc0.x); acc0.y = fmaf(o0.y, inv, acc0.y);
        acc0.z = fmaf(o0.z, inv, acc0.z); acc0.w = fmaf(o0.w, inv, acc0.w);
        acc1.x = fmaf(o1.x, inv, acc1.x); acc1.y = fmaf(o1.y, inv, acc1.y);
        acc1.z = fmaf(o1.z, inv, acc1.z); acc1.w = fmaf(o1.w, inv, acc1.w);
        acc2.x = fmaf(o2.x, inv, acc2.x); acc2.y = fmaf(o2.y, inv, acc2.y);
        acc2.z = fmaf(o2.z, inv, acc2.z); acc2.w = fmaf(o2.w, inv, acc2.w);
        acc3.x = fmaf(o3.x, inv, acc3.x); acc3.y = fmaf(o3.y, inv, acc3.y);
        acc3.z = fmaf(o3.z, inv, acc3.z); acc3.w = fmaf(o3.w, inv, acc3.w);
    }

    __syncthreads();
    float* red = asmem;
    float4* r4 = (float4*)(red + tid*20);
    r4[0] = acc0; r4[1] = acc1; r4[2] = acc2; r4[3] = acc3;
    __syncthreads();
    #pragma unroll
    for (int s = 128; s > 0; s >>= 1) {
        if (tid < s) {
            float* a_ = red + tid*20;
            const float* b_ = red + (tid + s)*20;
            #pragma unroll
            for (int d = 0; d < 16; d++) a_[d] += b_[d];
        }
        __syncthreads();
    }
    if (tid < 16) g_osum[bh*16 + tid] = red[tid];
}

// ---------------- final: tiny GEMV from partial sums ------------------------
__global__ __launch_bounds__(128) void reduce_kernel(
    const float* __restrict__ proj_w, const float* __restrict__ proj_b,
    const float* __restrict__ fc_w,   const float* __restrict__ fc_b,
    float* __restrict__ out) {
    int b = blockIdx.x, tid = threadIdx.x;
    __shared__ float meano[64], pooled[128];
    if (tid < 64) meano[tid] = g_osum[b*64 + tid] * (1.f/1024.f);
    float s = 0.f;
    #pragma unroll 4
    for (int Y = 0; Y < 32; Y++) s += g_fpart[(size_t)(b*32 + Y)*128 + tid];
    float pv = s * (1.f/1024.f) + proj_b[tid];
    __syncthreads();
    #pragma unroll 8
    for (int d = 0; d < 64; d++) pv = fmaf(proj_w[tid*64 + d], meano[d], pv);
    pooled[tid] = pv;
    __syncthreads();
    if (tid < 10) {
        float v2 = fc_b[tid];
        #pragma unroll 8
        for (int cc = 0; cc < 128; cc++) v2 = fmaf(fc_w[tid*128 + cc], pooled[cc], v2);
        out[b*10 + tid] = v2;
    }
}

// ---------------- launch ----------------------------------------------------
extern "C" void kernel_launch(void* const* d_in, const int* in_sizes, int n_in,
                              void* d_out, int out_size) {
    (void)in_sizes; (void)n_in; (void)out_size;
    const float* x       = (const float*)d_in[0];
    const float* conv1_w = (const float*)d_in[1];
    const float* conv1_b = (const float*)d_in[2];
    const float* conv2_w = (const float*)d_in[3];
    const float* conv2_b = (const float*)d_in[4];
    const float* q_w     = (const float*)d_in[5];
    const float* q_b     = (const float*)d_in[6];
    const float* k_w     = (const float*)d_in[7];
    const float* k_b     = (const float*)d_in[8];
    const float* v_w     = (const float*)d_in[9];
    const float* v_b     = (const float*)d_in[10];
    const float* proj_w  = (const float*)d_in[11];
    const float* proj_b  = (const float*)d_in[12];
    const float* rel_h   = (const float*)d_in[13];
    const float* rel_w   = (const float*)d_in[14];
    const float* fc_w    = (const float*)d_in[15];
    const float* fc_b    = (const float*)d_in[16];
    float* out = (float*)d_out;

    const int CONV2_SMEM = 69632;               // core 66560B, epilogue 67584B
    const int QKV_SMEM   = (16896 + 24576) * 4; // 165888 B
    const int ATTN_SMEM  = (32768 + 128) * 4;   // 131584 B
    cudaFuncSetAttribute(conv2_mma_kernel, cudaFuncAttributeMaxDynamicSharedMemorySize, CONV2_SMEM);
    cudaFuncSetAttribute(qkv_mma_kernel,  cudaFuncAttributeMaxDynamicSharedMemorySize, QKV_SMEM);
    cudaFuncSetAttribute(attn_fused_kernel, cudaFuncAttributeMaxDynamicSharedMemorySize, ATTN_SMEM);

    prep_kernel<<<272, 256>>>(conv2_w, q_w, k_w, v_w);
    conv1_kernel<<<dim3(8,32), 256>>>(x, conv1_w, conv1_b);
    conv2_mma_kernel<<<1024, 256, CONV2_SMEM>>>(conv2_b);
    qkv_mma_kernel<<<256, 256, QKV_SMEM>>>(q_b, k_b, v_b);
    attn_fused_kernel<<<128, 256, ATTN_SMEM>>>(rel_w, rel_h);
    reduce_kernel<<<32, 128>>>(proj_w, proj_b, fc_w, fc_b, out);
}

// round 17
// speedup vs baseline: 1.4109x; 1.0103x over previous
#include <cuda_runtime.h>
#include <cuda_fp16.h>
#include <cstdint>

// ---------------- scratch (static device globals; no allocations) ----------
__device__ __half2 g_h1h[32u*32*4356];   // conv1 out, packed ci-pairs: [b][ci2][66*66]
__device__ __half2 g_w2h[36864];         // conv2 weights, m16n8k16 fragment order
__device__ float g_wqkv[24576];          // qkv weights [192 x 128], fragment order (tf32)
__device__ float g_f [32u*32*32*128];    // conv2 out, NHWC, tf32-rounded values
__device__ float g_fpart[1024*128];      // per-conv2-CTA column sums of f (exact)
__device__ float g_q [32u*4*1024*16];    // [b,head,y,x,d]
__device__ float g_k [32u*4*1024*16];
__device__ float g_v [32u*4*1024*16];
__device__ float g_osum[128*16];         // per-(b,head) sum over tokens of (o_row+o_col)

// ---------------- helpers ----------------------------------------------------
__device__ __forceinline__ uint32_t smem_u32(const void* p) {
    uint32_t a;
    asm("{ .reg .u64 t; cvta.to.shared.u64 t, %1; cvt.u32.u64 %0, t; }"
        : "=r"(a) : "l"(p));
    return a;
}
__device__ __forceinline__ float tf32r(float x) {
    uint32_t u;
    asm("cvt.rna.tf32.f32 %0, %1;" : "=r"(u) : "f"(x));
    return __uint_as_float(u);
}
__device__ __forceinline__ void cpa16(uint32_t d, const void* s) {
    asm volatile("cp.async.cg.shared.global [%0], [%1], 16;" :: "r"(d), "l"(s));
}
__device__ __forceinline__ void mma16n8k8(float* c, const uint32_t* a, const uint32_t* b) {
    asm volatile("mma.sync.aligned.m16n8k8.row.col.f32.tf32.tf32.f32 "
        "{%0,%1,%2,%3}, {%4,%5,%6,%7}, {%8,%9}, {%0,%1,%2,%3};"
        : "+f"(c[0]), "+f"(c[1]), "+f"(c[2]), "+f"(c[3])
        : "r"(a[0]), "r"(a[1]), "r"(a[2]), "r"(a[3]), "r"(b[0]), "r"(b[1]));
}
__device__ __forceinline__ void mma16n8k16h(float* c, const uint32_t* a, const uint32_t* b) {
    asm volatile("mma.sync.aligned.m16n8k16.row.col.f32.f16.f16.f32 "
        "{%0,%1,%2,%3}, {%4,%5,%6,%7}, {%8,%9}, {%0,%1,%2,%3};"
        : "+f"(c[0]), "+f"(c[1]), "+f"(c[2]), "+f"(c[3])
        : "r"(a[0]), "r"(a[1]), "r"(a[2]), "r"(a[3]), "r"(b[0]), "r"(b[1]));
}
__device__ __forceinline__ float dot16(float4 q0, float4 q1, float4 q2, float4 q3,
                                       const float4* kp) {
    float4 k0 = kp[0], k1 = kp[1], k2 = kp[2], k3 = kp[3];
    float s = q0.x*k0.x;
    s = fmaf(q0.y, k0.y, s); s = fmaf(q0.z, k0.z, s); s = fmaf(q0.w, k0.w, s);
    s = fmaf(q1.x, k1.x, s); s = fmaf(q1.y, k1.y, s); s = fmaf(q1.z, k1.z, s); s = fmaf(q1.w, k1.w, s);
    s = fmaf(q2.x, k2.x, s); s = fmaf(q2.y, k2.y, s); s = fmaf(q2.z, k2.z, s); s = fmaf(q2.w, k2.w, s);
    s = fmaf(q3.x, k3.x, s); s = fmaf(q3.y, k3.y, s); s = fmaf(q3.z, k3.z, s); s = fmaf(q3.w, k3.w, s);
    return s;
}

// ---------------- merged prep: w2h | wqkv | h1h border zero -----------------
__global__ __launch_bounds__(256) void prep_kernel(const float* __restrict__ w2,
                                                   const float* __restrict__ qw,
                                                   const float* __restrict__ kw,
                                                   const float* __restrict__ vw) {
    int blk = blockIdx.x, tid = threadIdx.x;
    if (blk < 144) {                       // conv2 weights -> fp16 fragment order
        int i = blk * 256 + tid;           // i < 36864
        int t = i >> 12;
        int r = i & 4095;
        int z = r & 1;
        int lane = (r >> 1) & 31;
        int idx = r >> 6;
        int nf = idx & 15, g = idx >> 4;
        int co = nf * 8 + (lane >> 2);
        int k0 = g * 16 + (lane & 3) * 2 + z * 8;
        float w0 = w2[(co * 64 + k0) * 9 + t];
        float w1v = w2[(co * 64 + k0 + 1) * 9 + t];
        g_w2h[i] = __floats2half2_rn(w0, w1v);
    } else if (blk < 240) {                // qkv weights -> tf32 fragment order
        int i = (blk - 144) * 256 + tid;
        int z = i & 1;
        int lane = (i >> 1) & 31;
        int rest = i >> 6;
        int nf = rest % 24, ks = rest / 24;
        int o = nf * 8 + (lane >> 2);
        int k = ks * 8 + (lane & 3) + 4 * z;
        float v;
        if (o < 64)       v = qw[o*128 + k] * 0.25f;
        else if (o < 128) v = kw[(o-64)*128 + k];
        else              v = vw[(o-128)*128 + k];
        g_wqkv[i] = tf32r(v);
    } else {                               // zero h1h borders (32 ci2 x 260)
        int b = blk - 240;
        __half2 zz = __floats2half2_rn(0.f, 0.f);
        for (int i = tid; i < 8320; i += 256) {
            int ci2 = i / 260, j = i % 260;
            int p, q;
            if (j < 66)       { p = 0;           q = j; }
            else if (j < 132) { p = 65;          q = j - 66; }
            else if (j < 196) { p = j - 132 + 1; q = 0; }
            else              { p = j - 196 + 1; q = 65; }
            g_h1h[((size_t)b * 32 + ci2) * 4356 + p * 66 + q] = zz;
        }
    }
}

// ---------------- conv1 scalar, 2 pooled outputs/thread ---------------------
__global__ __launch_bounds__(256, 2) void conv1_kernel(const float* __restrict__ x,
                                                       const float* __restrict__ w,
                                                       const float* __restrict__ bias) {
    __shared__ float s_in[3*34*66];
    __shared__ float s_w[64*28];
    __shared__ float s_b[64];
    int b  = blockIdx.y;
    int tY = blockIdx.x >> 1, tX = blockIdx.x & 1;
    int Py0 = tY*16, Px0 = tX*32;
    int tid = threadIdx.x;

    for (int i = tid; i < 64*27; i += 256) {
        int co = i / 27, k = i - co*27;
        s_w[co*28 + k] = w[i];
    }
    if (tid < 64) { s_b[tid] = bias[tid]; s_w[tid*28 + 27] = 0.f; }

    const float* xb = x + (size_t)b*3*128*128;
    for (int i = tid; i < 3*34*66; i += 256) {
        int ci = i / 2244, rem2 = i % 2244;
        int ly = rem2 / 66, lx = rem2 % 66;
        int gy = 2*Py0 - 1 + ly, gx = 2*Px0 - 1 + lx;
        float v = 0.f;
        if (gy >= 0 && gy < 128 && gx >= 0 && gx < 128)
            v = xb[(size_t)ci*16384 + gy*128 + gx];
        s_in[i] = v;
    }
    __syncthreads();

    int ty = tid >> 4, tx2 = tid & 15;
    float win[3][24];
    #pragma unroll
    for (int ci = 0; ci < 3; ci++)
        #pragma unroll
        for (int r = 0; r < 4; r++)
            #pragma unroll
            for (int c = 0; c < 6; c++)
                win[ci][r*6+c] = s_in[ci*2244 + (2*ty + r)*66 + (4*tx2 + c)];

    int Y = Py0 + ty;
    int X0 = Px0 + 2*tx2;
    int pos0 = (Y + 1) * 66 + (X0 + 1);
    __half2* hb = g_h1h + (size_t)b * 32 * 4356;
    float prev[2];
    #pragma unroll 1
    for (int co = 0; co < 64; co++) {
        float wv[28];
        const float4* wp4 = reinterpret_cast<const float4*>(&s_w[co*28]);
        #pragma unroll
        for (int q4 = 0; q4 < 7; q4++) {
            float4 t4 = wp4[q4];
            wv[q4*4+0] = t4.x; wv[q4*4+1] = t4.y;
            wv[q4*4+2] = t4.z; wv[q4*4+3] = t4.w;
        }
        float a0[4] = {0.f,0.f,0.f,0.f};
        float a1[4] = {0.f,0.f,0.f,0.f};
        #pragma unroll
        for (int ci = 0; ci < 3; ci++)
            #pragma unroll
            for (int k = 0; k < 9; k++) {
                int ky = k/3, kx = k%3;
                float wvv = wv[ci*9+k];
                const float* wr0 = &win[ci][ ky   *6 + kx];
                const float* wr1 = &win[ci][(ky+1)*6 + kx];
                a0[0] = fmaf(wr0[0], wvv, a0[0]);
                a0[1] = fmaf(wr0[1], wvv, a0[1]);
                a0[2] = fmaf(wr1[0], wvv, a0[2]);
                a0[3] = fmaf(wr1[1], wvv, a0[3]);
                a1[0] = fmaf(wr0[2], wvv, a1[0]);
                a1[1] = fmaf(wr0[3], wvv, a1[1]);
                a1[2] = fmaf(wr1[2], wvv, a1[2]);
                a1[3] = fmaf(wr1[3], wvv, a1[3]);
            }
        float m0 = fmaxf(fmaxf(a0[0],a0[1]), fmaxf(a0[2],a0[3]));
        float m1 = fmaxf(fmaxf(a1[0],a1[1]), fmaxf(a1[2],a1[3]));
        float v0 = fmaxf(m0 + s_b[co], 0.f);
        float v1 = fmaxf(m1 + s_b[co], 0.f);
        if (co & 1) {
            __half2* dst = hb + (size_t)(co >> 1) * 4356 + pos0;
            dst[0] = __floats2half2_rn(prev[0], v0);
            dst[1] = __floats2half2_rn(prev[1], v1);
        } else {
            prev[0] = v0; prev[1] = v1;
        }
    }
}

// ---------------- conv2 via mma.sync f16 m16n8k16 (9 taps, M=128) -----------
__global__ __launch_bounds__(256, 2) void conv2_mma_kernel(const float* __restrict__ b2) {
    extern __shared__ float sm[];
    __half2* h2s = (__half2*)sm;
    const int tid = threadIdx.x;
    const int lane = tid & 31, wid = tid >> 5;
    const int warp_m = wid >> 1, warp_n = wid & 1;
    const int bY = blockIdx.x;
    const int b = bY >> 5, Y = bY & 31;

    uint32_t smb = smem_u32(sm);
    const uint32_t bufBb[2] = { smb + 33792u, smb + 50176u };
    const int bufBh[2] = { 8448, 12544 };

    {
        const __half2* src = g_h1h + (size_t)b * 32 * 4356 + 132 * Y;
        for (int i = tid; i < 2112; i += 256) {        // 32 ci2 x 66 x 16B
            int ci2 = i / 66, j = i - ci2 * 66;
            cpa16(smb + (uint32_t)(ci2 * 264 + j * 4) * 4u,
                  src + (size_t)ci2 * 4356 + j * 4);
        }
        for (int i = tid; i < 1024; i += 256)
            cpa16(bufBb[0] + (uint32_t)i * 16u, g_w2h + i * 4);
        asm volatile("cp.async.commit_group;" ::: "memory");
        for (int i = tid; i < 1024; i += 256)
            cpa16(bufBb[1] + (uint32_t)i * 16u, g_w2h + 4096 + i * 4);
        asm volatile("cp.async.commit_group;" ::: "memory");
    }

    float c[2][8][4];
    #pragma unroll
    for (int mf = 0; mf < 2; mf++)
        #pragma unroll
        for (int nf = 0; nf < 8; nf++)
            #pragma unroll
            for (int r = 0; r < 4; r++) c[mf][nf][r] = 0.f;

    const int ry  = warp_m >> 1;
    const int xw0 = (warp_m & 1) * 32;

    #pragma unroll 1
    for (int t = 0; t < 9; t++) {
        if (t < 8) { asm volatile("cp.async.wait_group 1;" ::: "memory"); }
        else       { asm volatile("cp.async.wait_group 0;" ::: "memory"); }
        __syncthreads();

        const int ky = t / 3, kx = t - ky * 3;
        const __half2* Abase = h2s + (ry + ky) * 66 + kx + xw0 + (lane >> 2)
                             + (lane & 3) * 264;
        const __half2* Bbase = h2s + bufBh[t & 1] + warp_n * 512 + lane * 2;
        #pragma unroll
        for (int g = 0; g < 4; g++) {
            const __half2* Ak = Abase + g * 2112;
            uint32_t a[2][4];
            #pragma unroll
            for (int mf = 0; mf < 2; mf++) {
                const __half2* Am = Ak + mf * 16;
                a[mf][0] = *reinterpret_cast<const uint32_t*>(Am);
                a[mf][1] = *reinterpret_cast<const uint32_t*>(Am + 8);
                a[mf][2] = *reinterpret_cast<const uint32_t*>(Am + 1056);
                a[mf][3] = *reinterpret_cast<const uint32_t*>(Am + 1064);
            }
            const __half2* Bk = Bbase + g * 1024;
            uint32_t bb[8][2];
            #pragma unroll
            for (int nf = 0; nf < 8; nf++) {
                uint2 v = *reinterpret_cast<const uint2*>(Bk + nf * 64);
                bb[nf][0] = v.x; bb[nf][1] = v.y;
            }
            #pragma unroll
            for (int mf = 0; mf < 2; mf++)
                #pragma unroll
                for (int nf = 0; nf < 8; nf++)
                    mma16n8k16h(c[mf][nf], a[mf], bb[nf]);
        }

        __syncthreads();
        if (t < 7) {
            const __half2* wsrc = g_w2h + (t + 2) * 4096;
            uint32_t dst = bufBb[t & 1];
            for (int i = tid; i < 1024; i += 256)
                cpa16(dst + (uint32_t)i * 16u, wsrc + i * 4);
            asm volatile("cp.async.commit_group;" ::: "memory");
        }
    }

    // ---- epilogue: stage C [128][132] f32, pool+bias+relu ----
    #pragma unroll
    for (int mf = 0; mf < 2; mf++)
        #pragma unroll
        for (int nf = 0; nf < 8; nf++) {
            int m0 = warp_m*32 + mf*16 + (lane >> 2);
            int n0 = warp_n*64 + nf*8 + (lane & 3)*2;
            *reinterpret_cast<float2*>(sm + m0*132 + n0)     = make_float2(c[mf][nf][0], c[mf][nf][1]);
            *reinterpret_cast<float2*>(sm + (m0+8)*132 + n0) = make_float2(c[mf][nf][2], c[mf][nf][3]);
        }
    __syncthreads();
    float* gf = g_f + (((size_t)b*32 + Y)*32)*128;
    float fsum = 0.f;
    #pragma unroll
    for (int u = 0; u < 16; u++) {
        int idx = tid + u*256;
        int cch = idx & 127, xo = idx >> 7;
        float v0 = fmaxf(sm[(2*xo)*132 + cch],    sm[(2*xo+1)*132 + cch]);
        float v1 = fmaxf(sm[(64+2*xo)*132 + cch], sm[(64+2*xo+1)*132 + cch]);
        float v = fmaxf(fmaxf(v0, v1) + __ldg(&b2[cch]), 0.f);
        fsum += v;
        gf[(size_t)xo*128 + cch] = tf32r(v);
    }
    __syncthreads();
    float* red = sm + 16896;
    red[tid] = fsum;
    __syncthreads();
    if (tid < 128) g_fpart[(size_t)bY*128 + tid] = red[tid] + red[tid+128];
}

// ---------------- qkv via mma.sync tf32 (proven R11, A-stride 136) ----------
// A: 128 tokens x 128 ch f32, smem row stride 136 (≡8 mod 32 -> conflict-free
// A-fragment loads, unlike old 132 ≡ 4 which 2-way conflicted).
__global__ __launch_bounds__(256) void qkv_mma_kernel(
    const float* __restrict__ qb, const float* __restrict__ kb,
    const float* __restrict__ vb) {
    extern __shared__ float sm[];
    const int tid = threadIdx.x;
    const int lane = tid & 31, wid = tid >> 5;
    const int warp_m = wid >> 1, warp_n = wid & 1;
    uint32_t smb = smem_u32(sm);

    {
        const float* gf0 = g_f + (size_t)blockIdx.x * 16384;
        for (int i = tid; i < 4096; i += 256) {
            int row = i >> 5, cg = i & 31;
            cpa16(smb + (uint32_t)(row * 136 + cg * 4) * 4u, gf0 + i * 4);
        }
        uint32_t bsb = smb + 17408u * 4u;
        for (int i = tid; i < 6144; i += 256)
            cpa16(bsb + (uint32_t)i * 16u, g_wqkv + i * 4);
        asm volatile("cp.async.commit_group;" ::: "memory");
        asm volatile("cp.async.wait_group 0;" ::: "memory");
    }
    __syncthreads();

    float c[2][12][4];
    #pragma unroll
    for (int mf = 0; mf < 2; mf++)
        #pragma unroll
        for (int nf = 0; nf < 12; nf++)
            #pragma unroll
            for (int r = 0; r < 4; r++) c[mf][nf][r] = 0.f;

    const float* Ab = sm + (warp_m * 32 + (lane >> 2)) * 136 + (lane & 3);
    const float* Bb = sm + 17408 + (warp_n * 12 * 64) + lane * 2;

    #pragma unroll 1
    for (int ks = 0; ks < 16; ks++) {
        uint32_t a[2][4];
        const float* Ak = Ab + ks * 8;
        #pragma unroll
        for (int mf = 0; mf < 2; mf++) {
            const float* Am = Ak + mf * 2176;        // 16 rows * 136
            a[mf][0] = __float_as_uint(Am[0]);
            a[mf][1] = __float_as_uint(Am[1088]);    // +8 rows
            a[mf][2] = __float_as_uint(Am[4]);       // k+4
            a[mf][3] = __float_as_uint(Am[1092]);
        }
        const float* Bk = Bb + ks * 1536;
        uint32_t bb[12][2];
        #pragma unroll
        for (int nf = 0; nf < 12; nf++) {
            float2 v = *reinterpret_cast<const float2*>(Bk + nf * 64);
            bb[nf][0] = __float_as_uint(v.x);
            bb[nf][1] = __float_as_uint(v.y);
        }
        #pragma unroll
        for (int mf = 0; mf < 2; mf++)
            #pragma unroll
            for (int nf = 0; nf < 12; nf++)
                mma16n8k8(c[mf][nf], a[mf], bb[nf]);
    }

    const int bb_  = blockIdx.x >> 3;
    const int rem0 = (blockIdx.x & 7) * 128 + warp_m * 32 + (lane >> 2);
    const int opair = (lane & 3) * 2;
    #pragma unroll
    for (int nf = 0; nf < 12; nf++) {
        int o = warp_n * 96 + nf * 8 + opair;
        float b0, b1; float* basep; int oo;
        if (o < 64)       { b0 = __ldg(&qb[o]) * 0.25f; b1 = __ldg(&qb[o+1]) * 0.25f; basep = g_q; oo = o; }
        else if (o < 128) { b0 = __ldg(&kb[o-64]);      b1 = __ldg(&kb[o-63]);        basep = g_k; oo = o-64; }
        else              { b0 = __ldg(&vb[o-128]);     b1 = __ldg(&vb[o-127]);       basep = g_v; oo = o-128; }
        int head = oo >> 4, d = oo & 15;
        float* hb = basep + ((size_t)(bb_ * 4 + head) * 1024) * 16 + d;
        #pragma unroll
        for (int mf = 0; mf < 2; mf++) {
            int rem = rem0 + mf * 16;
            *reinterpret_cast<float2*>(hb + (size_t)rem * 16)
                = make_float2(c[mf][nf][0] + b0, c[mf][nf][1] + b1);
            *reinterpret_cast<float2*>(hb + (size_t)(rem + 8) * 16)
                = make_float2(c[mf][nf][2] + b0, c[mf][nf][3] + b1);
        }
    }
}

// ---------------- fused axial attention (row + col), one CTA per (b,head) ---
__global__ __launch_bounds__(256) void attn_fused_kernel(const float* __restrict__ rel_w,
                                                         const float* __restrict__ rel_h) {
    extern __shared__ float asmem[];
    float* ks  = asmem;
    float* vs  = asmem + 16384;
    float* srw = asmem + 32768;
    float* srh = asmem + 32832;
    const int bh = blockIdx.x;
    const int head = bh & 3;
    const int tid = threadIdx.x;
    const int l = tid & 31, w = tid >> 5;

    {
        const float4* gk = (const float4*)(g_k + (size_t)bh * 16384);
        const float4* gv = (const float4*)(g_v + (size_t)bh * 16384);
        float4* k4 = (float4*)ks;
        float4* v4 = (float4*)vs;
        for (int i = tid; i < 4096; i += 256) { k4[i] = gk[i]; v4[i] = gv[i]; }
        if (tid < 63) { srw[tid] = rel_w[head*63 + tid]; srh[tid] = rel_h[head*63 + tid]; }
    }
    __syncthreads();

    const float* gq = g_q + (size_t)bh * 16384;
    float4 acc0 = {0,0,0,0}, acc1 = {0,0,0,0}, acc2 = {0,0,0,0}, acc3 = {0,0,0,0};

    #pragma unroll 1
    for (int u = 0; u < 4; u++) {
        const int y = w + 8*u;
        const int t = y*32 + l;
        const float4* qp = (const float4*)(gq + t*16);
        const float4 q0 = qp[0], q1 = qp[1], q2 = qp[2], q3 = qp[3];
        float sc[32];
        float mx = -1e30f;
        #pragma unroll
        for (int j = 0; j < 32; j++) {
            float s = dot16(q0, q1, q2, q3, (const float4*)(ks + (y*32 + j)*16));
            s += srw[l - j + 31];
            sc[j] = s;
            mx = fmaxf(mx, s);
        }
        float ssum = 0.f;
        #pragma unroll
        for (int j = 0; j < 32; j++) { sc[j] = __expf(sc[j] - mx); ssum += sc[j]; }
        const float inv = 1.f / ssum;
        float4 o0 = {0,0,0,0}, o1 = {0,0,0,0}, o2 = {0,0,0,0}, o3 = {0,0,0,0};
        #pragma unroll
        for (int j = 0; j < 32; j++) {
            const float4* vp = (const float4*)(vs + (y*32 + j)*16);
            const float p = sc[j];
            float4 v0 = vp[0], v1 = vp[1], v2 = vp[2], v3 = vp[3];
            o0.x = fmaf(p, v0.x, o0.x); o0.y = fmaf(p, v0.y, o0.y);
            o0.z = fmaf(p, v0.z, o0.z); o0.w = fmaf(p, v0.w, o0.w);
            o1.x = fmaf(p, v1.x, o1.x); o1.y = fmaf(p, v1.y, o1.y);
            o1.z = fmaf(p, v1.z, o1.z); o1.w = fmaf(p, v1.w, o1.w);
            o2.x = fmaf(p, v2.x, o2.x); o2.y = fmaf(p, v2.y, o2.y);
            o2.z = fmaf(p, v2.z, o2.z); o2.w = fmaf(p, v2.w, o2.w);
            o3.x = fmaf(p, v3.x, o3.x); o3.y = fmaf(p, v3.y, o3.y);
            o3.z = fmaf(p, v3.z, o3.z); o3.w = fmaf(p, v3.w, o3.w);
        }
        acc0.x = fmaf(o0.x, inv, acc0.x); acc0.y = fmaf(o0.y, inv, acc0.y);
        acc0.z = fmaf(o0.z, inv, acc0.z); acc0.w = fmaf(o0.w, inv, acc0.w);
        acc1.x = fmaf(o1.x, inv, acc1.x); acc1.y = fmaf(o1.y, inv, acc1.y);
        acc1.z = fmaf(o1.z, inv, acc1.z); acc1.w = fmaf(o1.w, inv, acc1.w);
        acc2.x = fmaf(o2.x, inv, acc2.x); acc2.y = fmaf(o2.y, inv, acc2.y);
        acc2.z = fmaf(o2.z, inv, acc2.z); acc2.w = fmaf(o2.w, inv, acc2.w);
        acc3.x = fmaf(o3.x, inv, acc3.x); acc3.y = fmaf(o3.y, inv, acc3.y);
        acc3.z = fmaf(o3.z, inv, acc3.z); acc3.w = fmaf(o3.w, inv, acc3.w);
    }

    #pragma unroll 1
    for (int u = 0; u < 4; u++) {
        const int x = w + 8*u;
        const int t = l*32 + x;
        const float4* qp = (const float4*)(gq + t*16);
        const float4 q0 = qp[0], q1 = qp[1], q2 = qp[2], q3 = qp[3];
        float sc[32];
        float mx = -1e30f;
        #pragma unroll
        for (int i = 0; i < 32; i++) {
            float s = dot16(q0, q1, q2, q3, (const float4*)(ks + (i*32 + x)*16));
            s += srh[l - i + 31];
            sc[i] = s;
            mx = fmaxf(mx, s);
        }
        float ssum = 0.f;
        #pragma unroll
        for (int i = 0; i < 32; i++) { sc[i] = __expf(sc[i] - mx); ssum += sc[i]; }
        const float inv = 1.f / ssum;
        float4 o0 = {0,0,0,0}, o1 = {0,0,0,0}, o2 = {0,0,0,0}, o3 = {0,0,0,0};
        #pragma unroll
        for (int i = 0; i < 32; i++) {
            const float4* vp = (const float4*)(vs + (i*32 + x)*16);
            const float p = sc[i];
            float4 v0 = vp[0], v1 = vp[1], v2 = vp[2], v3 = vp[3];
            o0.x = fmaf(p, v0.x, o0.x); o0.y = fmaf(p, v0.y, o0.y);
            o0.z = fmaf(p, v0.z, o0.z); o0.w = fmaf(p, v0.w, o0.w);
            o1.x = fmaf(p, v1.x, o1.x); o1.y = fmaf(p, v1.y, o1.y);
            o1.z = fmaf(p, v1.z, o1.z); o1.w = fmaf(p, v1.w, o1.w);
            o2.x = fmaf(p, v2.x, o2.x); o2.y = fmaf(p, v2.y, o2.y);
            o2.z = fmaf(p, v2.z, o2.z); o2.w = fmaf(p, v2.w, o2.w);
            o3.x = fmaf(p, v3.x, o3.x); o3.y = fmaf(p, v3.y, o3.y);
            o3.z = fmaf(p, v3.z, o3.z); o3.w = fmaf(p, v3.w, o3.w);
        }
        acc0.x = fmaf(o0.x, inv, acc0.x); acc0.y = fmaf(o0.y, inv, acc0.y);
        acc0.z = fmaf(o0.z, inv, acc0.z); acc0.w = fmaf(o0.w, inv, acc0.w);
        acc1.x = fmaf(o1.x, inv, acc1.x); acc1.y = fmaf(o1.y, inv, acc1.y);
        acc1.z = fmaf(o1.z, inv, acc1.z); acc1.w = fmaf(o1.w, inv, acc1.w);
        acc2.x = fmaf(o2.x, inv, acc2.x); acc2.y = fmaf(o2.y, inv, acc2.y);
        acc2.z = fmaf(o2.z, inv, acc2.z); acc2.w = fmaf(o2.w, inv, acc2.w);
        acc3.x = fmaf(o3.x, inv, acc3.x); acc3.y = fmaf(o3.y, inv, acc3.y);
        acc3.z = fmaf(o3.z, inv, acc3.z); acc3.w = fmaf(o3.w, inv, acc3.w);
    }

    __syncthreads();
    float* red = asmem;
    float4* r4 = (float4*)(red + tid*20);
    r4[0] = acc0; r4[1] = acc1; r4[2] = acc2; r4[3] = acc3;
    __syncthreads();
    #pragma unroll
    for (int s = 128; s > 0; s >>= 1) {
        if (tid < s) {
            float* a_ = red + tid*20;
            const float* b_ = red + (tid + s)*20;
            #pragma unroll
            for (int d = 0; d < 16; d++) a_[d] += b_[d];
        }
        __syncthreads();
    }
    if (tid < 16) g_osum[bh*16 + tid] = red[tid];
}

// ---------------- final: tiny GEMV from partial sums ------------------------
__global__ __launch_bounds__(128) void reduce_kernel(
    const float* __restrict__ proj_w, const float* __restrict__ proj_b,
    const float* __restrict__ fc_w,   const float* __restrict__ fc_b,
    float* __restrict__ out) {
    int b = blockIdx.x, tid = threadIdx.x;
    __shared__ float meano[64], pooled[128];
    if (tid < 64) meano[tid] = g_osum[b*64 + tid] * (1.f/1024.f);
    float s = 0.f;
    #pragma unroll 4
    for (int Y = 0; Y < 32; Y++) s += g_fpart[(size_t)(b*32 + Y)*128 + tid];
    float pv = s * (1.f/1024.f) + proj_b[tid];
    __syncthreads();
    #pragma unroll 8
    for (int d = 0; d < 64; d++) pv = fmaf(proj_w[tid*64 + d], meano[d], pv);
    pooled[tid] = pv;
    __syncthreads();
    if (tid < 10) {
        float v2 = fc_b[tid];
        #pragma unroll 8
        for (int cc = 0; cc < 128; cc++) v2 = fmaf(fc_w[tid*128 + cc], pooled[cc], v2);
        out[b*10 + tid] = v2;
    }
}

// ---------------- launch ----------------------------------------------------
extern "C" void kernel_launch(void* const* d_in, const int* in_sizes, int n_in,
                              void* d_out, int out_size) {
    (void)in_sizes; (void)n_in; (void)out_size;
    const float* x       = (const float*)d_in[0];
    const float* conv1_w = (const float*)d_in[1];
    const float* conv1_b = (const float*)d_in[2];
    const float* conv2_w = (const float*)d_in[3];
    const float* conv2_b = (const float*)d_in[4];
    const float* q_w     = (const float*)d_in[5];
    const float* q_b     = (const float*)d_in[6];
    const float* k_w     = (const float*)d_in[7];
    const float* k_b     = (const float*)d_in[8];
    const float* v_w     = (const float*)d_in[9];
    const float* v_b     = (const float*)d_in[10];
    const float* proj_w  = (const float*)d_in[11];
    const float* proj_b  = (const float*)d_in[12];
    const float* rel_h   = (const float*)d_in[13];
    const float* rel_w   = (const float*)d_in[14];
    const float* fc_w    = (const float*)d_in[15];
    const float* fc_b    = (const float*)d_in[16];
    float* out = (float*)d_out;

    const int CONV2_SMEM = 69632;               // core 66560B, epilogue 67584B
    const int QKV_SMEM   = (17408 + 24576) * 4; // 167936 B
    const int ATTN_SMEM  = (32768 + 128) * 4;   // 131584 B
    cudaFuncSetAttribute(conv2_mma_kernel, cudaFuncAttributeMaxDynamicSharedMemorySize, CONV2_SMEM);
    cudaFuncSetAttribute(qkv_mma_kernel,  cudaFuncAttributeMaxDynamicSharedMemorySize, QKV_SMEM);
    cudaFuncSetAttribute(attn_fused_kernel, cudaFuncAttributeMaxDynamicSharedMemorySize, ATTN_SMEM);

    prep_kernel<<<272, 256>>>(conv2_w, q_w, k_w, v_w);
    conv1_kernel<<<dim3(8,32), 256>>>(x, conv1_w, conv1_b);
    conv2_mma_kernel<<<1024, 256, CONV2_SMEM>>>(conv2_b);
    qkv_mma_kernel<<<256, 256, QKV_SMEM>>>(q_b, k_b, v_b);
    attn_fused_kernel<<<128, 256, ATTN_SMEM>>>(rel_w, rel_h);
    reduce_kernel<<<32, 128>>>(proj_w, proj_b, fc_w, fc_b, out);
}